// round 6
// baseline (speedup 1.0000x reference)
#include <cuda_runtime.h>
#include <cuda_bf16.h>
#include <math.h>
#include <stdint.h>

// Problem constants
#define B_ 2
#define L_ 4096
#define D_ 1024
#define H_ 16
#define DK_ 64
#define MROWS (B_*L_)          // 8192
#define BH (B_*H_)             // 32
#define NCHUNK 64
#define KX 3072                // expanded K (3x bf16 split)

// ---------------- scratch (device globals; allocation-free) ----------------
__device__ __align__(16) __nv_bfloat16 g_Ax  [MROWS*KX];   // x split  [M, 3072]  (hi|hi|lo)
__device__ __align__(16) __nv_bfloat16 g_Ao  [MROWS*KX];   // o split  [M, 3072]
__device__ __align__(16) __nv_bfloat16 g_Bqkv[3*D_*KX];    // Wq|Wk|Wv [3072 N, 3072 K] (hi|lo|hi)
__device__ __align__(16) __nv_bfloat16 g_Bo  [D_*KX];      // Wo       [1024 N, 3072 K]
__device__ float g_qkv[MROWS*3*D_];  // q|k|v linear outputs [M, 3072]
__device__ float g_qn [MROWS*D_];    // [bh][l][dk]
__device__ float g_kb [MROWS*D_];
__device__ float g_vs [MROWS*D_];
__device__ float g_beta [BH*L_];
__device__ float g_logf [BH*L_];
__device__ float g_logs [BH*L_];
__device__ float g_fw   [BH*L_];
__device__ float g_sw   [BH*L_];
__device__ float g_alpha[BH*L_];
__device__ float g_wsum [BH*2];
__device__ float g_part [BH*NCHUNK*2*DK_*DK_];
__device__ float g_M    [BH*2*DK_*DK_];

__device__ __forceinline__ float sigmoidf_(float x){ return 1.0f/(1.0f+expf(-x)); }

// ======================= PTX helpers (sm_80-compatible) =====================
__device__ __forceinline__ uint32_t smem_u32(const void* p){
    return (uint32_t)__cvta_generic_to_shared(p);
}
__device__ __forceinline__ void cp_async16(uint32_t saddr, const void* gaddr){
    asm volatile("cp.async.cg.shared.global [%0], [%1], 16;" :: "r"(saddr), "l"(gaddr));
}
__device__ __forceinline__ void cp_commit(){ asm volatile("cp.async.commit_group;"); }
#define CP_WAIT(n) asm volatile("cp.async.wait_group %0;" :: "n"(n))

__device__ __forceinline__ void ldmat_x4(uint32_t* r, uint32_t addr){
    asm volatile("ldmatrix.sync.aligned.m8n8.x4.shared.b16 {%0,%1,%2,%3}, [%4];"
        : "=r"(r[0]), "=r"(r[1]), "=r"(r[2]), "=r"(r[3]) : "r"(addr));
}
__device__ __forceinline__ void mma16816(float* c, const uint32_t* a, uint32_t b0, uint32_t b1){
    asm volatile("mma.sync.aligned.m16n8k16.row.col.f32.bf16.bf16.f32 "
        "{%0,%1,%2,%3}, {%4,%5,%6,%7}, {%8,%9}, {%0,%1,%2,%3};"
        : "+f"(c[0]), "+f"(c[1]), "+f"(c[2]), "+f"(c[3])
        : "r"(a[0]), "r"(a[1]), "r"(a[2]), "r"(a[3]), "r"(b0), "r"(b1));
}

// ====== HMMA bf16 GEMM: C[M,N] = A[M,K] * B[N,K]^T (both row-major, bf16) ===
// Block tile 256x128, K-chunk 32, 4-stage cp.async pipeline.
// 8 warps as 4M x 2N, warp tile 64x64.
#define BKC 32
#define SSTR 40                        // smem row stride in bf16 (80B, conflict-free)
#define GBM 256
#define GBN 128
#define ASZ (GBM*SSTR*2)               // 20480 B per A stage
#define BSZ (GBN*SSTR*2)               // 10240 B per B stage
#define STG (ASZ+BSZ)                  // 30720 B per stage
#define NSTAGE 4
#define GSMEM (NSTAGE*STG)             // 122880 B

__global__ __launch_bounds__(256, 1)
void gemm_bf16_mma(const __nv_bfloat16* __restrict__ A,
                   const __nv_bfloat16* __restrict__ B,
                   float* __restrict__ C, int M, int N, int K)
{
    extern __shared__ char sm[];
    const uint32_t sbase = smem_u32(sm);
    const int tid  = threadIdx.x;
    const int wid  = tid >> 5;
    const int lane = tid & 31;
    const int wm   = wid >> 1;       // 0..3 (64 rows each)
    const int wn   = wid & 1;        // 0..1 (64 cols each)

    const int m0 = blockIdx.y * GBM;
    const int n0 = blockIdx.x * GBN;
    const __nv_bfloat16* Ag = A + (size_t)m0 * K;
    const __nv_bfloat16* Bg = B + (size_t)n0 * K;

    // global->smem load mapping: 16B segments
    const int lrow = tid >> 2;           // 0..63
    const int lcol = (tid & 3) * 8;      // bf16 col {0,8,16,24}

    // ldmatrix lane offsets (byte offsets within a stage)
    const int arow = (lane & 15);
    const int akof = (lane >> 4) * 8;
    uint32_t aoff[4];
    #pragma unroll
    for (int mi = 0; mi < 4; mi++)
        aoff[mi] = (uint32_t)((wm*64 + mi*16 + arow) * SSTR + akof) * 2;

    const int brow = (lane & 7) + ((lane >> 4) << 3);
    const int bkof = ((lane >> 3) & 1) * 8;
    uint32_t boff[4];
    #pragma unroll
    for (int ni = 0; ni < 4; ni++)
        boff[ni] = (uint32_t)(ASZ) + (uint32_t)((wn*64 + ni*16 + brow) * SSTR + bkof) * 2;

    float acc[4][8][4];
    #pragma unroll
    for (int mi = 0; mi < 4; mi++)
        #pragma unroll
        for (int j = 0; j < 8; j++)
            #pragma unroll
            for (int t = 0; t < 4; t++) acc[mi][j][t] = 0.0f;

    const int nch = K / BKC;

    // prologue: load stages 0..NSTAGE-2
    #pragma unroll
    for (int s = 0; s < NSTAGE - 1; s++) {
        const size_t kc = (size_t)s * BKC;
        const uint32_t sa = sbase + s * STG;
        const uint32_t sb = sa + ASZ;
        #pragma unroll
        for (int t = 0; t < 4; t++) {
            const int r = lrow + t * 64;
            cp_async16(sa + (uint32_t)(r * SSTR + lcol) * 2, Ag + (size_t)r * K + kc + lcol);
        }
        #pragma unroll
        for (int t = 0; t < 2; t++) {
            const int r = lrow + t * 64;
            cp_async16(sb + (uint32_t)(r * SSTR + lcol) * 2, Bg + (size_t)r * K + kc + lcol);
        }
        cp_commit();
    }

    for (int c = 0; c < nch; c++) {
        CP_WAIT(NSTAGE - 2);
        __syncthreads();

        // prefetch chunk c + NSTAGE-1 (overlaps with compute below)
        {
            const int cn = c + NSTAGE - 1;
            if (cn < nch) {
                const int s = cn & (NSTAGE - 1);
                const size_t kc = (size_t)cn * BKC;
                const uint32_t sa = sbase + s * STG;
                const uint32_t sb = sa + ASZ;
                #pragma unroll
                for (int t = 0; t < 4; t++) {
                    const int r = lrow + t * 64;
                    cp_async16(sa + (uint32_t)(r * SSTR + lcol) * 2, Ag + (size_t)r * K + kc + lcol);
                }
                #pragma unroll
                for (int t = 0; t < 2; t++) {
                    const int r = lrow + t * 64;
                    cp_async16(sb + (uint32_t)(r * SSTR + lcol) * 2, Bg + (size_t)r * K + kc + lcol);
                }
            }
            cp_commit();
        }

        const uint32_t so = sbase + (uint32_t)(c & (NSTAGE - 1)) * STG;
        #pragma unroll
        for (int kk = 0; kk < 2; kk++) {
            const uint32_t ko = (uint32_t)(kk * 16) * 2;
            uint32_t a[4][4];
            #pragma unroll
            for (int mi = 0; mi < 4; mi++) ldmat_x4(a[mi], so + aoff[mi] + ko);
            uint32_t bf[4][4];
            #pragma unroll
            for (int ni = 0; ni < 4; ni++) ldmat_x4(bf[ni], so + boff[ni] + ko);
            #pragma unroll
            for (int mi = 0; mi < 4; mi++)
                #pragma unroll
                for (int ni = 0; ni < 4; ni++) {
                    mma16816(acc[mi][ni*2+0], a[mi], bf[ni][0], bf[ni][1]);
                    mma16816(acc[mi][ni*2+1], a[mi], bf[ni][2], bf[ni][3]);
                }
        }
    }

    // epilogue: direct fp32 stores
    const int rr = lane >> 2;
    const int cc = (lane & 3) * 2;
    #pragma unroll
    for (int mi = 0; mi < 4; mi++) {
        const int rowb = m0 + wm*64 + mi*16;
        #pragma unroll
        for (int j = 0; j < 8; j++) {
            const int col = n0 + wn*64 + j*8 + cc;
            float2 v0 = make_float2(acc[mi][j][0], acc[mi][j][1]);
            float2 v1 = make_float2(acc[mi][j][2], acc[mi][j][3]);
            *(float2*)(C + (size_t)(rowb + rr)     * N + col) = v0;
            *(float2*)(C + (size_t)(rowb + rr + 8) * N + col) = v1;
        }
    }
}

// ---------------- conversion: x -> bf16 split [hi|hi|lo] ----------------
__global__ __launch_bounds__(256) void convert_x_kernel(const float* __restrict__ x)
{
    const int idx = blockIdx.x * 256 + threadIdx.x;
    const int m  = idx >> 8;
    const int c4 = (idx & 255) * 4;
    float4 v = *(const float4*)(x + (size_t)m * D_ + c4);
    float vv[4] = {v.x, v.y, v.z, v.w};
    __nv_bfloat16 hi[4], lo[4];
    #pragma unroll
    for (int i = 0; i < 4; i++) {
        hi[i] = __float2bfloat16(vv[i]);
        lo[i] = __float2bfloat16(vv[i] - __bfloat162float(hi[i]));
    }
    __nv_bfloat16* dst = g_Ax + (size_t)m * KX + c4;
    *(uint2*)(dst)        = *(uint2*)hi;
    *(uint2*)(dst + 1024) = *(uint2*)hi;
    *(uint2*)(dst + 2048) = *(uint2*)lo;
}

// ---------------- conversion: W[K,N] -> Bt[N,3K] split [hi|lo|hi] ----------------
__global__ __launch_bounds__(1024) void convert_w_kernel(const float* __restrict__ W,
                                                         __nv_bfloat16* __restrict__ Bt,
                                                         int nrow_off)
{
    __shared__ float t[32][33];
    const int tx = threadIdx.x & 31, ty = threadIdx.x >> 5;
    const int n0 = blockIdx.x * 32, k0 = blockIdx.y * 32;
    t[ty][tx] = W[(size_t)(k0 + ty) * D_ + n0 + tx];
    __syncthreads();
    const float v = t[tx][ty];   // = W[k0+tx][n0+ty]
    const __nv_bfloat16 hi = __float2bfloat16(v);
    const __nv_bfloat16 lo = __float2bfloat16(v - __bfloat162float(hi));
    __nv_bfloat16* dst = Bt + (size_t)(nrow_off + n0 + ty) * KX + k0 + tx;
    dst[0]    = hi;
    dst[1024] = lo;
    dst[2048] = hi;
}

// ---------------- K2: small projections as tiled GEMM (128 tok x 48 out) ----
__global__ __launch_bounds__(256) void smallproj_kernel(const float* __restrict__ x,
                                                        const float* __restrict__ Wb,
                                                        const float* __restrict__ Wfd,
                                                        const float* __restrict__ bfd,
                                                        const float* __restrict__ Wsd,
                                                        const float* __restrict__ bsd)
{
    __shared__ float xs[128][65];
    __shared__ float ws[64][48];
    const int tid = threadIdx.x;
    const int m0  = blockIdx.x * 128;
    const int tok = tid & 127;
    const int og  = (tid >> 7) * 24;

    float acc[24];
    #pragma unroll
    for (int j = 0; j < 24; j++) acc[j] = 0.0f;

    for (int k0 = 0; k0 < D_; k0 += 64) {
        for (int i = tid; i < 2048; i += 256) {
            const int r = i >> 4, c = (i & 15) * 4;
            float4 v = *(const float4*)(x + (size_t)(m0 + r) * D_ + k0 + c);
            xs[r][c] = v.x; xs[r][c+1] = v.y; xs[r][c+2] = v.z; xs[r][c+3] = v.w;
        }
        for (int i = tid; i < 3072; i += 256) {
            const int k = i / 48, o = i % 48;
            const float* W = (o < 16) ? Wb : ((o < 32) ? Wfd : Wsd);
            ws[k][o] = W[(size_t)(k0 + k) * 16 + (o & 15)];
        }
        __syncthreads();
        #pragma unroll 8
        for (int k = 0; k < 64; k++) {
            const float xv = xs[tok][k];
            #pragma unroll
            for (int j = 0; j < 24; j++) acc[j] = fmaf(xv, ws[k][og + j], acc[j]);
        }
        __syncthreads();
    }

    const int m = m0 + tok;
    const int b = m >> 12;
    const int l = m & (L_-1);
    #pragma unroll
    for (int j = 0; j < 24; j++) {
        const int o = og + j;
        const int which = o >> 4, h = o & 15;
        const size_t idx = ((size_t)b*H_ + h)*L_ + l;
        if (which == 0)      g_beta[idx] = sigmoidf_(acc[j]);
        else if (which == 1) g_logf[idx] = logf(sigmoidf_(acc[j] + bfd[h]) + 1e-6f);
        else                 g_logs[idx] = logf(sigmoidf_(acc[j] + bsd[h]) + 1e-6f);
    }
}

// ---------------- K3: per-token prep ----------------
__global__ __launch_bounds__(128) void prep_kernel(const float* __restrict__ Wtf1,
                                                   const float* __restrict__ btf1,
                                                   const float* __restrict__ Wtf2,
                                                   const float* __restrict__ btf2)
{
    const int wip  = threadIdx.x >> 5;
    const int lane = threadIdx.x & 31;
    const size_t w = (size_t)blockIdx.x*4 + wip;
    const int bh = (int)(w / L_);
    const int l  = (int)(w % L_);
    const int b  = bh >> 4;
    const int h  = bh & 15;

    __shared__ float kbs[4][DK_];

    const size_t src = ((size_t)b*L_ + l)*(3*D_) + (size_t)h*DK_;
    float q0 = g_qkv[src + lane],          q1 = g_qkv[src + 32 + lane];
    float k0 = g_qkv[src + 1024 + lane],   k1 = g_qkv[src + 1024 + 32 + lane];
    float v0 = g_qkv[src + 2048 + lane],   v1 = g_qkv[src + 2048 + 32 + lane];

    float sq = q0*q0 + q1*q1;
    #pragma unroll
    for (int off = 16; off; off >>= 1) sq += __shfl_xor_sync(0xffffffffu, sq, off);
    float qinv = 1.0f / fmaxf(sqrtf(sq), 1e-12f);

    float sk = k0*k0 + k1*k1;
    #pragma unroll
    for (int off = 16; off; off >>= 1) sk += __shfl_xor_sync(0xffffffffu, sk, off);
    float kinv = 1.0f / fmaxf(sqrtf(sk), 1e-12f);

    const float beta = g_beta[(size_t)bh*L_ + l];
    const float kb0 = k0*kinv*beta, kb1 = k1*kinv*beta;

    const size_t dst = ((size_t)bh*L_ + l)*DK_;
    g_qn[dst + lane]      = q0*qinv;
    g_qn[dst + 32 + lane] = q1*qinv;
    g_kb[dst + lane]      = kb0;
    g_kb[dst + 32 + lane] = kb1;
    g_vs[dst + lane]      = v0*beta;
    g_vs[dst + 32 + lane] = v1*beta;

    kbs[wip][lane]      = kb0;
    kbs[wip][lane + 32] = kb1;
    __syncwarp();

    float hsum = btf1[lane];
    #pragma unroll 8
    for (int d = 0; d < DK_; d++) hsum = fmaf(kbs[wip][d], Wtf1[d*32 + lane], hsum);
    float sil = hsum / (1.0f + expf(-hsum));
    float acc = sil * Wtf2[lane];
    #pragma unroll
    for (int off = 16; off; off >>= 1) acc += __shfl_xor_sync(0xffffffffu, acc, off);

    if (lane == 0) {
        float tf = sigmoidf_(acc + btf2[0]);
        tf = fminf(fmaxf(tf, 0.01f), 0.99f);
        g_alpha[(size_t)bh*L_ + l] = 0.5f + 0.3f*tf;
    }
}

// ---------------- K4: per-(b,h) cumsum scan (double) ----------------
__global__ __launch_bounds__(256) void scan_kernel()
{
    const int bh  = blockIdx.x;
    const int tid = threadIdx.x;
    const int PER = L_ / 256;
    __shared__ double s[256];

    for (int fs = 0; fs < 2; fs++) {
        const float* lg = (fs == 0) ? g_logf : g_logs;
        float*       wv = (fs == 0) ? g_fw   : g_sw;

        double loc[16];
        double run = 0.0;
        const size_t base = (size_t)bh*L_ + (size_t)tid*PER;
        #pragma unroll
        for (int i = 0; i < PER; i++) { run += (double)lg[base + i]; loc[i] = run; }
        s[tid] = run;
        __syncthreads();
        for (int off = 1; off < 256; off <<= 1) {
            double v = (tid >= off) ? s[tid - off] : 0.0;
            __syncthreads();
            s[tid] += v;
            __syncthreads();
        }
        const double excl  = s[tid] - run;
        const double total = s[255];
        __syncthreads();

        double acc = 0.0;
        #pragma unroll
        for (int i = 0; i < PER; i++) {
            double ww = exp(total - (excl + loc[i]));
            wv[base + i] = (float)ww;
            acc += ww;
        }
        s[tid] = acc;
        __syncthreads();
        for (int off = 128; off > 0; off >>= 1) {
            if (tid < off) s[tid] += s[tid + off];
            __syncthreads();
        }
        if (tid == 0) g_wsum[bh*2 + fs] = (float)s[0];
        __syncthreads();
    }
}

// ---------------- K5: partial KV outer-product states ----------------
__global__ __launch_bounds__(256) void outer_kernel()
{
    const int bh  = blockIdx.y;
    const int ch  = blockIdx.x;
    const int tid = threadIdx.x;
    __shared__ float ks [64*64];
    __shared__ float vsh[64*64];
    __shared__ float fsh[64], ssh[64];

    const int l0 = ch * 64;
    const float* kbp = g_kb + ((size_t)bh*L_ + l0)*DK_;
    const float* vsp = g_vs + ((size_t)bh*L_ + l0)*DK_;
    for (int i = tid*4; i < 4096; i += 1024) {
        *(float4*)(ks + i)  = *(const float4*)(kbp + i);
        *(float4*)(vsh + i) = *(const float4*)(vsp + i);
    }
    if (tid < 64) {
        fsh[tid] = g_fw[(size_t)bh*L_ + l0 + tid];
        ssh[tid] = g_sw[(size_t)bh*L_ + l0 + tid];
    }
    __syncthreads();

    const int d0 = (tid >> 4) * 4;
    const int e0 = (tid & 15) * 4;
    float af[4][4], as_[4][4];
    #pragma unroll
    for (int i = 0; i < 4; i++)
        #pragma unroll
        for (int j = 0; j < 4; j++) { af[i][j] = 0.f; as_[i][j] = 0.f; }

    for (int ll = 0; ll < 64; ll++) {
        const float f = fsh[ll], sdec = ssh[ll];
        float kd[4], ve[4];
        #pragma unroll
        for (int i = 0; i < 4; i++) kd[i] = ks[ll*64 + d0 + i];
        #pragma unroll
        for (int j = 0; j < 4; j++) ve[j] = vsh[ll*64 + e0 + j];
        #pragma unroll
        for (int i = 0; i < 4; i++) {
            const float kf = kd[i]*f, ksl = kd[i]*sdec;
            #pragma unroll
            for (int j = 0; j < 4; j++) {
                af[i][j]  = fmaf(kf,  ve[j], af[i][j]);
                as_[i][j] = fmaf(ksl, ve[j], as_[i][j]);
            }
        }
    }

    float* pf = g_part + ((size_t)(bh*NCHUNK + ch))*8192;
    #pragma unroll
    for (int i = 0; i < 4; i++)
        #pragma unroll
        for (int j = 0; j < 4; j++) {
            pf[(d0+i)*64 + e0 + j]        = af[i][j];
            pf[4096 + (d0+i)*64 + e0 + j] = as_[i][j];
        }
}

// ---------------- K6: reduce partials + normalize ----------------
__global__ __launch_bounds__(256) void reduce_kernel()
{
    const int bh  = blockIdx.x;
    const int tid = threadIdx.x;
    for (int idx = tid; idx < 8192; idx += 256) {
        const int fs = idx >> 12;
        float sum = 0.0f;
        for (int c = 0; c < NCHUNK; c++)
            sum += g_part[((size_t)(bh*NCHUNK + c))*8192 + idx];
        g_M[(size_t)bh*8192 + idx] = sum / (g_wsum[bh*2 + fs] + 1e-6f);
    }
}

// ---------------- K7: output mix -> writes bf16 split A for final GEMM ------
__global__ __launch_bounds__(256) void outproj_kernel()
{
    const int bh  = blockIdx.y;
    const int lt  = blockIdx.x;
    const int tid = threadIdx.x;
    __shared__ float qs[32*64];
    __shared__ float Mf[64*64];
    __shared__ float Ms[64*64];
    __shared__ float al[32];

    const int l0 = lt * 32;
    const float* qp = g_qn + ((size_t)bh*L_ + l0)*DK_;
    for (int i = tid*4; i < 2048; i += 1024) *(float4*)(qs + i) = *(const float4*)(qp + i);
    const float* Mp = g_M + (size_t)bh*8192;
    for (int i = tid*4; i < 4096; i += 1024) {
        *(float4*)(Mf + i) = *(const float4*)(Mp + i);
        *(float4*)(Ms + i) = *(const float4*)(Mp + 4096 + i);
    }
    if (tid < 32) al[tid] = g_alpha[(size_t)bh*L_ + l0 + tid];
    __syncthreads();

    const int li = tid >> 3;
    const int e0 = (tid & 7) * 8;
    float of[8], os[8];
    #pragma unroll
    for (int j = 0; j < 8; j++) { of[j] = 0.f; os[j] = 0.f; }

    #pragma unroll 4
    for (int d = 0; d < 64; d++) {
        const float qv = qs[li*64 + d];
        #pragma unroll
        for (int j = 0; j < 8; j++) {
            of[j] = fmaf(qv, Mf[d*64 + e0 + j], of[j]);
            os[j] = fmaf(qv, Ms[d*64 + e0 + j], os[j]);
        }
    }
    const float a = al[li];
    const int b = bh >> 4, h = bh & 15;
    const size_t m = (size_t)b*L_ + l0 + li;
    __nv_bfloat16 hi[8], lo[8];
    #pragma unroll
    for (int j = 0; j < 8; j++) {
        const float val = a*of[j] + (1.0f - a)*os[j];
        hi[j] = __float2bfloat16(val);
        lo[j] = __float2bfloat16(val - __bfloat162float(hi[j]));
    }
    __nv_bfloat16* dst = g_Ao + m*KX + (size_t)h*DK_ + e0;
    *(uint4*)(dst)        = *(uint4*)hi;
    *(uint4*)(dst + 1024) = *(uint4*)hi;
    *(uint4*)(dst + 2048) = *(uint4*)lo;
}

// ---------------- launch ----------------
extern "C" void kernel_launch(void* const* d_in, const int* in_sizes, int n_in,
                              void* d_out, int out_size)
{
    const float* x    = (const float*)d_in[0];
    const float* Wq   = (const float*)d_in[1];
    const float* Wk   = (const float*)d_in[2];
    const float* Wv   = (const float*)d_in[3];
    const float* Wb   = (const float*)d_in[4];
    const float* Wo   = (const float*)d_in[5];
    const float* Wfd  = (const float*)d_in[6];
    const float* bfd  = (const float*)d_in[7];
    const float* Wsd  = (const float*)d_in[8];
    const float* bsd  = (const float*)d_in[9];
    const float* Wtf1 = (const float*)d_in[10];
    const float* btf1 = (const float*)d_in[11];
    const float* Wtf2 = (const float*)d_in[12];
    const float* btf2 = (const float*)d_in[13];
    float* out = (float*)d_out;

    __nv_bfloat16 *Ax, *Ao, *Bqkv, *Bo;
    float *qkv;
    cudaGetSymbolAddress((void**)&Ax,   g_Ax);
    cudaGetSymbolAddress((void**)&Ao,   g_Ao);
    cudaGetSymbolAddress((void**)&Bqkv, g_Bqkv);
    cudaGetSymbolAddress((void**)&Bo,   g_Bo);
    cudaGetSymbolAddress((void**)&qkv,  g_qkv);

    cudaFuncSetAttribute(gemm_bf16_mma, cudaFuncAttributeMaxDynamicSharedMemorySize, GSMEM);

    // conversions
    convert_x_kernel<<<(MROWS * D_ / 4) / 256, 256>>>(x);
    dim3 wgrid(D_/32, D_/32);
    convert_w_kernel<<<wgrid, 1024>>>(Wq, Bqkv, 0);
    convert_w_kernel<<<wgrid, 1024>>>(Wk, Bqkv, 1024);
    convert_w_kernel<<<wgrid, 1024>>>(Wv, Bqkv, 2048);
    convert_w_kernel<<<wgrid, 1024>>>(Wo, Bo, 0);

    // fused q|k|v GEMM: [8192, 3072] = Ax[8192,3072k] * Bqkv[3072n,3072k]^T
    dim3 qkvgrid(3*D_/GBN, MROWS/GBM);   // (24, 32)
    gemm_bf16_mma<<<qkvgrid, 256, GSMEM>>>(Ax, Bqkv, qkv, MROWS, 3*D_, KX);

    smallproj_kernel<<<MROWS/128, 256>>>(x, Wb, Wfd, bfd, Wsd, bsd);
    prep_kernel<<<(BH * L_) / 4, 128>>>(Wtf1, btf1, Wtf2, btf2);
    scan_kernel<<<BH, 256>>>();

    dim3 ogrid(NCHUNK, BH);
    outer_kernel<<<ogrid, 256>>>();
    reduce_kernel<<<BH, 256>>>();

    dim3 pgrid(L_ / 32, BH);
    outproj_kernel<<<pgrid, 256>>>();

    // final GEMM: out[8192,1024] = Ao[8192,3072k] * Bo[1024n,3072k]^T
    dim3 fgrid(D_/GBN, MROWS/GBM);       // (8, 32)
    gemm_bf16_mma<<<fgrid, 256, GSMEM>>>(Ao, Bo, out, MROWS, D_, KX);
}

// round 7
// speedup vs baseline: 1.1170x; 1.1170x over previous
#include <cuda_runtime.h>
#include <cuda_bf16.h>
#include <math.h>
#include <stdint.h>

// Problem constants
#define B_ 2
#define L_ 4096
#define D_ 1024
#define H_ 16
#define DK_ 64
#define MROWS (B_*L_)          // 8192
#define BH (B_*H_)             // 32
#define NCHUNK 64
#define KX 3072                // expanded K (3x bf16 split)

// ---------------- scratch (device globals; allocation-free) ----------------
__device__ __align__(16) __nv_bfloat16 g_Ax  [MROWS*KX];   // x split  [M, 3072]  (hi|hi|lo)
__device__ __align__(16) __nv_bfloat16 g_Ao  [MROWS*KX];   // o split  [M, 3072]
__device__ __align__(16) __nv_bfloat16 g_Bqkv[3*D_*KX];    // Wq|Wk|Wv [3072 N, 3072 K] (hi|lo|hi)
__device__ __align__(16) __nv_bfloat16 g_Bo  [D_*KX];      // Wo       [1024 N, 3072 K]
__device__ float g_qkv[MROWS*3*D_];  // q|k|v linear outputs [M, 3072]
__device__ float g_qn [MROWS*D_];    // [bh][l][dk]
__device__ float g_kb [MROWS*D_];
__device__ float g_vs [MROWS*D_];
__device__ float g_beta [BH*L_];
__device__ float g_logf [BH*L_];
__device__ float g_logs [BH*L_];
__device__ float g_fw   [BH*L_];
__device__ float g_sw   [BH*L_];
__device__ float g_alpha[BH*L_];
__device__ float g_wsum [BH*2];
__device__ float g_part [BH*NCHUNK*2*DK_*DK_];
__device__ float g_M    [BH*2*DK_*DK_];

__device__ __forceinline__ float sigmoidf_(float x){ return 1.0f/(1.0f+expf(-x)); }

// ======================= PTX helpers (sm_80-compatible) =====================
__device__ __forceinline__ uint32_t smem_u32(const void* p){
    return (uint32_t)__cvta_generic_to_shared(p);
}
__device__ __forceinline__ void cp_async16(uint32_t saddr, const void* gaddr){
    asm volatile("cp.async.cg.shared.global [%0], [%1], 16;" :: "r"(saddr), "l"(gaddr));
}
__device__ __forceinline__ void cp_commit(){ asm volatile("cp.async.commit_group;"); }
#define CP_WAIT(n) asm volatile("cp.async.wait_group %0;" :: "n"(n))

__device__ __forceinline__ void ldmat_x4(uint32_t* r, uint32_t addr){
    asm volatile("ldmatrix.sync.aligned.m8n8.x4.shared.b16 {%0,%1,%2,%3}, [%4];"
        : "=r"(r[0]), "=r"(r[1]), "=r"(r[2]), "=r"(r[3]) : "r"(addr));
}
__device__ __forceinline__ void mma16816(float* c, const uint32_t* a, uint32_t b0, uint32_t b1){
    asm volatile("mma.sync.aligned.m16n8k16.row.col.f32.bf16.bf16.f32 "
        "{%0,%1,%2,%3}, {%4,%5,%6,%7}, {%8,%9}, {%0,%1,%2,%3};"
        : "+f"(c[0]), "+f"(c[1]), "+f"(c[2]), "+f"(c[3])
        : "r"(a[0]), "r"(a[1]), "r"(a[2]), "r"(a[3]), "r"(b0), "r"(b1));
}

// ====== HMMA bf16 GEMM: C[M,N] = A[M,K] * B[N,K]^T (both row-major, bf16) ===
// Block tile 128x128, K-chunk 32, 4-stage cp.async pipeline, 2 CTAs/SM.
// 8 warps as 4M x 2N, warp tile 32x64.
#define BKC 32
#define SSTR 40                        // smem row stride in bf16 (80B, conflict-free)
#define HTILE (128*SSTR*2)             // 10240 B (one operand per stage)
#define STG (2*HTILE)                  // 20480 B per stage (A+B)
#define NST 4
#define GSMEM (NST*STG)                // 81920 B

__global__ __launch_bounds__(256, 2)
void gemm_bf16_mma(const __nv_bfloat16* __restrict__ A,
                   const __nv_bfloat16* __restrict__ B,
                   float* __restrict__ C, int M, int N, int K)
{
    extern __shared__ char sm[];
    const uint32_t sbase = smem_u32(sm);
    const int tid  = threadIdx.x;
    const int wid  = tid >> 5;
    const int lane = tid & 31;
    const int wm   = wid & 3;        // warp M index (0..3)
    const int wn   = wid >> 2;       // warp N index (0..1)

    const int m0 = blockIdx.y * 128;
    const int n0 = blockIdx.x * 128;
    const __nv_bfloat16* Ag = A + (size_t)m0 * K;
    const __nv_bfloat16* Bg = B + (size_t)n0 * K;

    // global->smem mapping: 2 x 16B segments per thread per operand
    const int r0s = tid >> 2;             // 0..63
    const int r1s = r0s + 64;             // 64..127
    const int cs  = (tid & 3) * 8;        // bf16 col {0,8,16,24}
    const uint32_t oA0 = (uint32_t)(r0s * SSTR + cs) * 2;
    const uint32_t oA1 = (uint32_t)(r1s * SSTR + cs) * 2;
    const uint32_t oB0 = HTILE + oA0;
    const uint32_t oB1 = HTILE + oA1;

    // ldmatrix lane offsets (byte offsets within a stage)
    const int arow = (lane & 15);
    const int akof = (lane >> 4) * 8;
    uint32_t aoff[2];
    #pragma unroll
    for (int mi = 0; mi < 2; mi++)
        aoff[mi] = (uint32_t)((wm*32 + mi*16 + arow) * SSTR + akof) * 2;

    const int brow = (lane & 7) + ((lane >> 4) << 3);
    const int bkof = ((lane >> 3) & 1) * 8;
    uint32_t boff[4];
    #pragma unroll
    for (int ni = 0; ni < 4; ni++)
        boff[ni] = HTILE + (uint32_t)((wn*64 + ni*16 + brow) * SSTR + bkof) * 2;

    float acc[2][8][4];
    #pragma unroll
    for (int mi = 0; mi < 2; mi++)
        #pragma unroll
        for (int j = 0; j < 8; j++)
            #pragma unroll
            for (int t = 0; t < 4; t++) acc[mi][j][t] = 0.0f;

    const int nch = K / BKC;

    // prologue: load chunks 0..NST-2 into stages 0..NST-2
    #pragma unroll
    for (int s = 0; s < NST - 1; s++) {
        const size_t kc = (size_t)s * BKC;
        const uint32_t sa = sbase + s * STG;
        cp_async16(sa + oA0, Ag + (size_t)r0s * K + kc + cs);
        cp_async16(sa + oA1, Ag + (size_t)r1s * K + kc + cs);
        cp_async16(sa + oB0, Bg + (size_t)r0s * K + kc + cs);
        cp_async16(sa + oB1, Bg + (size_t)r1s * K + kc + cs);
        cp_commit();
    }

    for (int c = 0; c < nch; c++) {
        CP_WAIT(NST - 2);
        __syncthreads();

        // prefetch chunk c+NST-1 into stage (c+NST-1)%NST (== stage of iter c-1)
        {
            const int cn = c + NST - 1;
            if (cn < nch) {
                const size_t kc = (size_t)cn * BKC;
                const uint32_t sa = sbase + (uint32_t)(cn & (NST - 1)) * STG;
                cp_async16(sa + oA0, Ag + (size_t)r0s * K + kc + cs);
                cp_async16(sa + oA1, Ag + (size_t)r1s * K + kc + cs);
                cp_async16(sa + oB0, Bg + (size_t)r0s * K + kc + cs);
                cp_async16(sa + oB1, Bg + (size_t)r1s * K + kc + cs);
            }
            cp_commit();
        }

        const uint32_t so = sbase + (uint32_t)(c & (NST - 1)) * STG;
        #pragma unroll
        for (int kk = 0; kk < 2; kk++) {
            const uint32_t ko = (uint32_t)(kk * 16) * 2;
            uint32_t a[2][4];
            #pragma unroll
            for (int mi = 0; mi < 2; mi++) ldmat_x4(a[mi], so + aoff[mi] + ko);
            uint32_t bf[4][4];
            #pragma unroll
            for (int ni = 0; ni < 4; ni++) ldmat_x4(bf[ni], so + boff[ni] + ko);
            #pragma unroll
            for (int mi = 0; mi < 2; mi++)
                #pragma unroll
                for (int ni = 0; ni < 4; ni++) {
                    mma16816(acc[mi][ni*2+0], a[mi], bf[ni][0], bf[ni][1]);
                    mma16816(acc[mi][ni*2+1], a[mi], bf[ni][2], bf[ni][3]);
                }
        }
    }

    // epilogue: direct fp32 stores
    const int rr = lane >> 2;
    const int cc = (lane & 3) * 2;
    #pragma unroll
    for (int mi = 0; mi < 2; mi++) {
        const int rowb = m0 + wm*32 + mi*16;
        #pragma unroll
        for (int j = 0; j < 8; j++) {
            const int col = n0 + wn*64 + j*8 + cc;
            float2 v0 = make_float2(acc[mi][j][0], acc[mi][j][1]);
            float2 v1 = make_float2(acc[mi][j][2], acc[mi][j][3]);
            *(float2*)(C + (size_t)(rowb + rr)     * N + col) = v0;
            *(float2*)(C + (size_t)(rowb + rr + 8) * N + col) = v1;
        }
    }
}

// ---------------- conversion: x -> bf16 split [hi|hi|lo] ----------------
__global__ __launch_bounds__(256) void convert_x_kernel(const float* __restrict__ x)
{
    const int idx = blockIdx.x * 256 + threadIdx.x;
    const int m  = idx >> 8;
    const int c4 = (idx & 255) * 4;
    float4 v = *(const float4*)(x + (size_t)m * D_ + c4);
    float vv[4] = {v.x, v.y, v.z, v.w};
    __nv_bfloat16 hi[4], lo[4];
    #pragma unroll
    for (int i = 0; i < 4; i++) {
        hi[i] = __float2bfloat16(vv[i]);
        lo[i] = __float2bfloat16(vv[i] - __bfloat162float(hi[i]));
    }
    __nv_bfloat16* dst = g_Ax + (size_t)m * KX + c4;
    *(uint2*)(dst)        = *(uint2*)hi;
    *(uint2*)(dst + 1024) = *(uint2*)hi;
    *(uint2*)(dst + 2048) = *(uint2*)lo;
}

// ------- conversion: all four W[K,N] -> Bt[N,3K] split [hi|lo|hi], z-grid ----
__global__ __launch_bounds__(1024) void convert_w_kernel(const float* __restrict__ Wq,
                                                         const float* __restrict__ Wk,
                                                         const float* __restrict__ Wv,
                                                         const float* __restrict__ Wo)
{
    __shared__ float t[32][33];
    const int z  = blockIdx.z;
    const float* W = (z == 0) ? Wq : ((z == 1) ? Wk : ((z == 2) ? Wv : Wo));
    __nv_bfloat16* Bt;
    if (z < 3) { Bt = g_Bqkv + (size_t)z * 1024 * KX; }
    else       { Bt = g_Bo; }

    const int tx = threadIdx.x & 31, ty = threadIdx.x >> 5;
    const int n0 = blockIdx.x * 32, k0 = blockIdx.y * 32;
    t[ty][tx] = W[(size_t)(k0 + ty) * D_ + n0 + tx];
    __syncthreads();
    const float v = t[tx][ty];   // = W[k0+tx][n0+ty]
    const __nv_bfloat16 hi = __float2bfloat16(v);
    const __nv_bfloat16 lo = __float2bfloat16(v - __bfloat162float(hi));
    __nv_bfloat16* dst = Bt + (size_t)(n0 + ty) * KX + k0 + tx;
    dst[0]    = hi;
    dst[1024] = lo;
    dst[2048] = hi;
}

// ---------------- K2: small projections as tiled GEMM (128 tok x 48 out) ----
__global__ __launch_bounds__(256) void smallproj_kernel(const float* __restrict__ x,
                                                        const float* __restrict__ Wb,
                                                        const float* __restrict__ Wfd,
                                                        const float* __restrict__ bfd,
                                                        const float* __restrict__ Wsd,
                                                        const float* __restrict__ bsd)
{
    __shared__ float xs[128][65];
    __shared__ float ws[64][48];
    const int tid = threadIdx.x;
    const int m0  = blockIdx.x * 128;
    const int tok = tid & 127;
    const int og  = (tid >> 7) * 24;

    float acc[24];
    #pragma unroll
    for (int j = 0; j < 24; j++) acc[j] = 0.0f;

    for (int k0 = 0; k0 < D_; k0 += 64) {
        for (int i = tid; i < 2048; i += 256) {
            const int r = i >> 4, c = (i & 15) * 4;
            float4 v = *(const float4*)(x + (size_t)(m0 + r) * D_ + k0 + c);
            xs[r][c] = v.x; xs[r][c+1] = v.y; xs[r][c+2] = v.z; xs[r][c+3] = v.w;
        }
        for (int i = tid; i < 3072; i += 256) {
            const int k = i / 48, o = i % 48;
            const float* W = (o < 16) ? Wb : ((o < 32) ? Wfd : Wsd);
            ws[k][o] = W[(size_t)(k0 + k) * 16 + (o & 15)];
        }
        __syncthreads();
        #pragma unroll 8
        for (int k = 0; k < 64; k++) {
            const float xv = xs[tok][k];
            #pragma unroll
            for (int j = 0; j < 24; j++) acc[j] = fmaf(xv, ws[k][og + j], acc[j]);
        }
        __syncthreads();
    }

    const int m = m0 + tok;
    const int b = m >> 12;
    const int l = m & (L_-1);
    #pragma unroll
    for (int j = 0; j < 24; j++) {
        const int o = og + j;
        const int which = o >> 4, h = o & 15;
        const size_t idx = ((size_t)b*H_ + h)*L_ + l;
        if (which == 0)      g_beta[idx] = sigmoidf_(acc[j]);
        else if (which == 1) g_logf[idx] = logf(sigmoidf_(acc[j] + bfd[h]) + 1e-6f);
        else                 g_logs[idx] = logf(sigmoidf_(acc[j] + bsd[h]) + 1e-6f);
    }
}

// ---------------- K3: per-token prep ----------------
__global__ __launch_bounds__(128) void prep_kernel(const float* __restrict__ Wtf1,
                                                   const float* __restrict__ btf1,
                                                   const float* __restrict__ Wtf2,
                                                   const float* __restrict__ btf2)
{
    const int wip  = threadIdx.x >> 5;
    const int lane = threadIdx.x & 31;
    const size_t w = (size_t)blockIdx.x*4 + wip;
    const int bh = (int)(w / L_);
    const int l  = (int)(w % L_);
    const int b  = bh >> 4;
    const int h  = bh & 15;

    __shared__ float kbs[4][DK_];

    const size_t src = ((size_t)b*L_ + l)*(3*D_) + (size_t)h*DK_;
    float q0 = g_qkv[src + lane],          q1 = g_qkv[src + 32 + lane];
    float k0 = g_qkv[src + 1024 + lane],   k1 = g_qkv[src + 1024 + 32 + lane];
    float v0 = g_qkv[src + 2048 + lane],   v1 = g_qkv[src + 2048 + 32 + lane];

    float sq = q0*q0 + q1*q1;
    #pragma unroll
    for (int off = 16; off; off >>= 1) sq += __shfl_xor_sync(0xffffffffu, sq, off);
    float qinv = 1.0f / fmaxf(sqrtf(sq), 1e-12f);

    float sk = k0*k0 + k1*k1;
    #pragma unroll
    for (int off = 16; off; off >>= 1) sk += __shfl_xor_sync(0xffffffffu, sk, off);
    float kinv = 1.0f / fmaxf(sqrtf(sk), 1e-12f);

    const float beta = g_beta[(size_t)bh*L_ + l];
    const float kb0 = k0*kinv*beta, kb1 = k1*kinv*beta;

    const size_t dst = ((size_t)bh*L_ + l)*DK_;
    g_qn[dst + lane]      = q0*qinv;
    g_qn[dst + 32 + lane] = q1*qinv;
    g_kb[dst + lane]      = kb0;
    g_kb[dst + 32 + lane] = kb1;
    g_vs[dst + lane]      = v0*beta;
    g_vs[dst + 32 + lane] = v1*beta;

    kbs[wip][lane]      = kb0;
    kbs[wip][lane + 32] = kb1;
    __syncwarp();

    float hsum = btf1[lane];
    #pragma unroll 8
    for (int d = 0; d < DK_; d++) hsum = fmaf(kbs[wip][d], Wtf1[d*32 + lane], hsum);
    float sil = hsum / (1.0f + expf(-hsum));
    float acc = sil * Wtf2[lane];
    #pragma unroll
    for (int off = 16; off; off >>= 1) acc += __shfl_xor_sync(0xffffffffu, acc, off);

    if (lane == 0) {
        float tf = sigmoidf_(acc + btf2[0]);
        tf = fminf(fmaxf(tf, 0.01f), 0.99f);
        g_alpha[(size_t)bh*L_ + l] = 0.5f + 0.3f*tf;
    }
}

// ---------------- K4: per-(b,h) cumsum scan (double) ----------------
__global__ __launch_bounds__(256) void scan_kernel()
{
    const int bh  = blockIdx.x;
    const int tid = threadIdx.x;
    const int PER = L_ / 256;
    __shared__ double s[256];

    for (int fs = 0; fs < 2; fs++) {
        const float* lg = (fs == 0) ? g_logf : g_logs;
        float*       wv = (fs == 0) ? g_fw   : g_sw;

        double loc[16];
        double run = 0.0;
        const size_t base = (size_t)bh*L_ + (size_t)tid*PER;
        #pragma unroll
        for (int i = 0; i < PER; i++) { run += (double)lg[base + i]; loc[i] = run; }
        s[tid] = run;
        __syncthreads();
        for (int off = 1; off < 256; off <<= 1) {
            double v = (tid >= off) ? s[tid - off] : 0.0;
            __syncthreads();
            s[tid] += v;
            __syncthreads();
        }
        const double excl  = s[tid] - run;
        const double total = s[255];
        __syncthreads();

        double acc = 0.0;
        #pragma unroll
        for (int i = 0; i < PER; i++) {
            double ww = exp(total - (excl + loc[i]));
            wv[base + i] = (float)ww;
            acc += ww;
        }
        s[tid] = acc;
        __syncthreads();
        for (int off = 128; off > 0; off >>= 1) {
            if (tid < off) s[tid] += s[tid + off];
            __syncthreads();
        }
        if (tid == 0) g_wsum[bh*2 + fs] = (float)s[0];
        __syncthreads();
    }
}

// ---------------- K5: partial KV outer-product states ----------------
__global__ __launch_bounds__(256) void outer_kernel()
{
    const int bh  = blockIdx.y;
    const int ch  = blockIdx.x;
    const int tid = threadIdx.x;
    __shared__ float ks [64*64];
    __shared__ float vsh[64*64];
    __shared__ float fsh[64], ssh[64];

    const int l0 = ch * 64;
    const float* kbp = g_kb + ((size_t)bh*L_ + l0)*DK_;
    const float* vsp = g_vs + ((size_t)bh*L_ + l0)*DK_;
    for (int i = tid*4; i < 4096; i += 1024) {
        *(float4*)(ks + i)  = *(const float4*)(kbp + i);
        *(float4*)(vsh + i) = *(const float4*)(vsp + i);
    }
    if (tid < 64) {
        fsh[tid] = g_fw[(size_t)bh*L_ + l0 + tid];
        ssh[tid] = g_sw[(size_t)bh*L_ + l0 + tid];
    }
    __syncthreads();

    const int d0 = (tid >> 4) * 4;
    const int e0 = (tid & 15) * 4;
    float af[4][4], as_[4][4];
    #pragma unroll
    for (int i = 0; i < 4; i++)
        #pragma unroll
        for (int j = 0; j < 4; j++) { af[i][j] = 0.f; as_[i][j] = 0.f; }

    for (int ll = 0; ll < 64; ll++) {
        const float f = fsh[ll], sdec = ssh[ll];
        float kd[4], ve[4];
        #pragma unroll
        for (int i = 0; i < 4; i++) kd[i] = ks[ll*64 + d0 + i];
        #pragma unroll
        for (int j = 0; j < 4; j++) ve[j] = vsh[ll*64 + e0 + j];
        #pragma unroll
        for (int i = 0; i < 4; i++) {
            const float kf = kd[i]*f, ksl = kd[i]*sdec;
            #pragma unroll
            for (int j = 0; j < 4; j++) {
                af[i][j]  = fmaf(kf,  ve[j], af[i][j]);
                as_[i][j] = fmaf(ksl, ve[j], as_[i][j]);
            }
        }
    }

    float* pf = g_part + ((size_t)(bh*NCHUNK + ch))*8192;
    #pragma unroll
    for (int i = 0; i < 4; i++)
        #pragma unroll
        for (int j = 0; j < 4; j++) {
            pf[(d0+i)*64 + e0 + j]        = af[i][j];
            pf[4096 + (d0+i)*64 + e0 + j] = as_[i][j];
        }
}

// ---------------- K6: reduce partials + normalize ----------------
__global__ __launch_bounds__(256) void reduce_kernel()
{
    const int bh  = blockIdx.x;
    const int tid = threadIdx.x;
    for (int idx = tid; idx < 8192; idx += 256) {
        const int fs = idx >> 12;
        float sum = 0.0f;
        for (int c = 0; c < NCHUNK; c++)
            sum += g_part[((size_t)(bh*NCHUNK + c))*8192 + idx];
        g_M[(size_t)bh*8192 + idx] = sum / (g_wsum[bh*2 + fs] + 1e-6f);
    }
}

// ---------------- K7: output mix -> writes bf16 split A for final GEMM ------
__global__ __launch_bounds__(256) void outproj_kernel()
{
    const int bh  = blockIdx.y;
    const int lt  = blockIdx.x;
    const int tid = threadIdx.x;
    __shared__ float qs[32*64];
    __shared__ float Mf[64*64];
    __shared__ float Ms[64*64];
    __shared__ float al[32];

    const int l0 = lt * 32;
    const float* qp = g_qn + ((size_t)bh*L_ + l0)*DK_;
    for (int i = tid*4; i < 2048; i += 1024) *(float4*)(qs + i) = *(const float4*)(qp + i);
    const float* Mp = g_M + (size_t)bh*8192;
    for (int i = tid*4; i < 4096; i += 1024) {
        *(float4*)(Mf + i) = *(const float4*)(Mp + i);
        *(float4*)(Ms + i) = *(const float4*)(Mp + 4096 + i);
    }
    if (tid < 32) al[tid] = g_alpha[(size_t)bh*L_ + l0 + tid];
    __syncthreads();

    const int li = tid >> 3;
    const int e0 = (tid & 7) * 8;
    float of[8], os[8];
    #pragma unroll
    for (int j = 0; j < 8; j++) { of[j] = 0.f; os[j] = 0.f; }

    #pragma unroll 4
    for (int d = 0; d < 64; d++) {
        const float qv = qs[li*64 + d];
        #pragma unroll
        for (int j = 0; j < 8; j++) {
            of[j] = fmaf(qv, Mf[d*64 + e0 + j], of[j]);
            os[j] = fmaf(qv, Ms[d*64 + e0 + j], os[j]);
        }
    }
    const float a = al[li];
    const int b = bh >> 4, h = bh & 15;
    const size_t m = (size_t)b*L_ + l0 + li;
    __nv_bfloat16 hi[8], lo[8];
    #pragma unroll
    for (int j = 0; j < 8; j++) {
        const float val = a*of[j] + (1.0f - a)*os[j];
        hi[j] = __float2bfloat16(val);
        lo[j] = __float2bfloat16(val - __bfloat162float(hi[j]));
    }
    __nv_bfloat16* dst = g_Ao + m*KX + (size_t)h*DK_ + e0;
    *(uint4*)(dst)        = *(uint4*)hi;
    *(uint4*)(dst + 1024) = *(uint4*)hi;
    *(uint4*)(dst + 2048) = *(uint4*)lo;
}

// ---------------- launch ----------------
extern "C" void kernel_launch(void* const* d_in, const int* in_sizes, int n_in,
                              void* d_out, int out_size)
{
    const float* x    = (const float*)d_in[0];
    const float* Wq   = (const float*)d_in[1];
    const float* Wk   = (const float*)d_in[2];
    const float* Wv   = (const float*)d_in[3];
    const float* Wb   = (const float*)d_in[4];
    const float* Wo   = (const float*)d_in[5];
    const float* Wfd  = (const float*)d_in[6];
    const float* bfd  = (const float*)d_in[7];
    const float* Wsd  = (const float*)d_in[8];
    const float* bsd  = (const float*)d_in[9];
    const float* Wtf1 = (const float*)d_in[10];
    const float* btf1 = (const float*)d_in[11];
    const float* Wtf2 = (const float*)d_in[12];
    const float* btf2 = (const float*)d_in[13];
    float* out = (float*)d_out;

    __nv_bfloat16 *Ax, *Ao, *Bqkv, *Bo;
    float *qkv;
    cudaGetSymbolAddress((void**)&Ax,   g_Ax);
    cudaGetSymbolAddress((void**)&Ao,   g_Ao);
    cudaGetSymbolAddress((void**)&Bqkv, g_Bqkv);
    cudaGetSymbolAddress((void**)&Bo,   g_Bo);
    cudaGetSymbolAddress((void**)&qkv,  g_qkv);

    cudaFuncSetAttribute(gemm_bf16_mma, cudaFuncAttributeMaxDynamicSharedMemorySize, GSMEM);

    // conversions
    convert_x_kernel<<<(MROWS * D_ / 4) / 256, 256>>>(x);
    dim3 wgrid(D_/32, D_/32, 4);
    convert_w_kernel<<<wgrid, 1024>>>(Wq, Wk, Wv, Wo);

    // fused q|k|v GEMM: [8192, 3072] = Ax[8192,3072k] * Bqkv[3072n,3072k]^T
    dim3 qkvgrid(3*D_/128, MROWS/128);   // (24, 64)
    gemm_bf16_mma<<<qkvgrid, 256, GSMEM>>>(Ax, Bqkv, qkv, MROWS, 3*D_, KX);

    smallproj_kernel<<<MROWS/128, 256>>>(x, Wb, Wfd, bfd, Wsd, bsd);
    prep_kernel<<<(BH * L_) / 4, 128>>>(Wtf1, btf1, Wtf2, btf2);
    scan_kernel<<<BH, 256>>>();

    dim3 ogrid(NCHUNK, BH);
    outer_kernel<<<ogrid, 256>>>();
    reduce_kernel<<<BH, 256>>>();

    dim3 pgrid(L_ / 32, BH);
    outproj_kernel<<<pgrid, 256>>>();

    // final GEMM: out[8192,1024] = Ao[8192,3072k] * Bo[1024n,3072k]^T
    dim3 fgrid(D_/128, MROWS/128);       // (8, 64)
    gemm_bf16_mma<<<fgrid, 256, GSMEM>>>(Ao, Bo, out, MROWS, D_, KX);
}

// round 10
// speedup vs baseline: 1.2015x; 1.0756x over previous
#include <cuda_runtime.h>
#include <cuda_bf16.h>
#include <math.h>
#include <stdint.h>

// Problem constants
#define B_ 2
#define L_ 4096
#define D_ 1024
#define H_ 16
#define DK_ 64
#define MROWS (B_*L_)          // 8192
#define BH (B_*H_)             // 32
#define NCHUNK 16              // 256 tokens per partial chunk
#define CHT 256                // tokens per chunk
#define KX 3072                // expanded K (3x bf16 split)

// ---------------- scratch (device globals; allocation-free) ----------------
__device__ __align__(16) __nv_bfloat16 g_Ax  [MROWS*KX];   // x split  [M, 3072]  (hi|hi|lo)
__device__ __align__(16) __nv_bfloat16 g_Ao  [MROWS*KX];   // o split  [M, 3072]
__device__ __align__(16) __nv_bfloat16 g_Bqkv[3*D_*KX];    // Wq|Wk|Wv [3072 N, 3072 K] (hi|lo|hi)
__device__ __align__(16) __nv_bfloat16 g_Bo  [D_*KX];      // Wo       [1024 N, 3072 K]
__device__ float g_qkv[MROWS*3*D_];  // q|k|v linear outputs [M, 3072]
__device__ float g_qn [MROWS*D_];    // [bh][l][dk]
__device__ float g_kb [MROWS*D_];
__device__ float g_vs [MROWS*D_];
__device__ float g_beta [BH*L_];
__device__ float g_logf [BH*L_];
__device__ float g_logs [BH*L_];
__device__ float g_fw   [BH*L_];
__device__ float g_sw   [BH*L_];
__device__ float g_alpha[BH*L_];
__device__ float g_wsum [BH*2];
__device__ float g_part [BH*NCHUNK*2*DK_*DK_];   // 4.2M floats
__device__ float g_M    [BH*2*DK_*DK_];

__device__ __forceinline__ float sigmoidf_(float x){ return 1.0f/(1.0f+expf(-x)); }

// ======================= PTX helpers (sm_80-compatible) =====================
__device__ __forceinline__ uint32_t smem_u32(const void* p){
    return (uint32_t)__cvta_generic_to_shared(p);
}
__device__ __forceinline__ void cp_async16(uint32_t saddr, const void* gaddr){
    asm volatile("cp.async.cg.shared.global [%0], [%1], 16;" :: "r"(saddr), "l"(gaddr));
}
__device__ __forceinline__ void cp_commit(){ asm volatile("cp.async.commit_group;"); }
#define CP_WAIT(n) asm volatile("cp.async.wait_group %0;" :: "n"(n))

__device__ __forceinline__ void ldmat_x4(uint32_t* r, uint32_t addr){
    asm volatile("ldmatrix.sync.aligned.m8n8.x4.shared.b16 {%0,%1,%2,%3}, [%4];"
        : "=r"(r[0]), "=r"(r[1]), "=r"(r[2]), "=r"(r[3]) : "r"(addr));
}
__device__ __forceinline__ void mma16816(float* c, const uint32_t* a, uint32_t b0, uint32_t b1){
    asm volatile("mma.sync.aligned.m16n8k16.row.col.f32.bf16.bf16.f32 "
        "{%0,%1,%2,%3}, {%4,%5,%6,%7}, {%8,%9}, {%0,%1,%2,%3};"
        : "+f"(c[0]), "+f"(c[1]), "+f"(c[2]), "+f"(c[3])
        : "r"(a[0]), "r"(a[1]), "r"(a[2]), "r"(a[3]), "r"(b0), "r"(b1));
}

// ====== HMMA bf16 GEMM: C[M,N] = A[M,K] * B[N,K]^T (both row-major, bf16) ===
// Block tile 128x128, K-chunk 32, 4-stage cp.async pipeline, 2 CTAs/SM.
#define BKC 32
#define SSTR 40                        // smem row stride in bf16 (80B, conflict-free)
#define HTILE (128*SSTR*2)             // 10240 B (one operand per stage)
#define STG (2*HTILE)                  // 20480 B per stage (A+B)
#define NST 4
#define GSMEM (NST*STG)                // 81920 B

__global__ __launch_bounds__(256, 2)
void gemm_bf16_mma(const __nv_bfloat16* __restrict__ A,
                   const __nv_bfloat16* __restrict__ B,
                   float* __restrict__ C, int M, int N, int K)
{
    extern __shared__ char sm[];
    const uint32_t sbase = smem_u32(sm);
    const int tid  = threadIdx.x;
    const int wid  = tid >> 5;
    const int lane = tid & 31;
    const int wm   = wid & 3;
    const int wn   = wid >> 2;

    const int m0 = blockIdx.y * 128;
    const int n0 = blockIdx.x * 128;
    const __nv_bfloat16* Ag = A + (size_t)m0 * K;
    const __nv_bfloat16* Bg = B + (size_t)n0 * K;

    const int r0s = tid >> 2;
    const int r1s = r0s + 64;
    const int cs  = (tid & 3) * 8;
    const uint32_t oA0 = (uint32_t)(r0s * SSTR + cs) * 2;
    const uint32_t oA1 = (uint32_t)(r1s * SSTR + cs) * 2;
    const uint32_t oB0 = HTILE + oA0;
    const uint32_t oB1 = HTILE + oA1;

    const int arow = (lane & 15);
    const int akof = (lane >> 4) * 8;
    uint32_t aoff[2];
    #pragma unroll
    for (int mi = 0; mi < 2; mi++)
        aoff[mi] = (uint32_t)((wm*32 + mi*16 + arow) * SSTR + akof) * 2;

    const int brow = (lane & 7) + ((lane >> 4) << 3);
    const int bkof = ((lane >> 3) & 1) * 8;
    uint32_t boff[4];
    #pragma unroll
    for (int ni = 0; ni < 4; ni++)
        boff[ni] = HTILE + (uint32_t)((wn*64 + ni*16 + brow) * SSTR + bkof) * 2;

    float acc[2][8][4];
    #pragma unroll
    for (int mi = 0; mi < 2; mi++)
        #pragma unroll
        for (int j = 0; j < 8; j++)
            #pragma unroll
            for (int t = 0; t < 4; t++) acc[mi][j][t] = 0.0f;

    const int nch = K / BKC;

    #pragma unroll
    for (int s = 0; s < NST - 1; s++) {
        const size_t kc = (size_t)s * BKC;
        const uint32_t sa = sbase + s * STG;
        cp_async16(sa + oA0, Ag + (size_t)r0s * K + kc + cs);
        cp_async16(sa + oA1, Ag + (size_t)r1s * K + kc + cs);
        cp_async16(sa + oB0, Bg + (size_t)r0s * K + kc + cs);
        cp_async16(sa + oB1, Bg + (size_t)r1s * K + kc + cs);
        cp_commit();
    }

    for (int c = 0; c < nch; c++) {
        CP_WAIT(NST - 2);
        __syncthreads();

        {
            const int cn = c + NST - 1;
            if (cn < nch) {
                const size_t kc = (size_t)cn * BKC;
                const uint32_t sa = sbase + (uint32_t)(cn & (NST - 1)) * STG;
                cp_async16(sa + oA0, Ag + (size_t)r0s * K + kc + cs);
                cp_async16(sa + oA1, Ag + (size_t)r1s * K + kc + cs);
                cp_async16(sa + oB0, Bg + (size_t)r0s * K + kc + cs);
                cp_async16(sa + oB1, Bg + (size_t)r1s * K + kc + cs);
            }
            cp_commit();
        }

        const uint32_t so = sbase + (uint32_t)(c & (NST - 1)) * STG;
        #pragma unroll
        for (int kk = 0; kk < 2; kk++) {
            const uint32_t ko = (uint32_t)(kk * 16) * 2;
            uint32_t a[2][4];
            #pragma unroll
            for (int mi = 0; mi < 2; mi++) ldmat_x4(a[mi], so + aoff[mi] + ko);
            uint32_t bf[4][4];
            #pragma unroll
            for (int ni = 0; ni < 4; ni++) ldmat_x4(bf[ni], so + boff[ni] + ko);
            #pragma unroll
            for (int mi = 0; mi < 2; mi++)
                #pragma unroll
                for (int ni = 0; ni < 4; ni++) {
                    mma16816(acc[mi][ni*2+0], a[mi], bf[ni][0], bf[ni][1]);
                    mma16816(acc[mi][ni*2+1], a[mi], bf[ni][2], bf[ni][3]);
                }
        }
    }

    const int rr = lane >> 2;
    const int cc = (lane & 3) * 2;
    #pragma unroll
    for (int mi = 0; mi < 2; mi++) {
        const int rowb = m0 + wm*32 + mi*16;
        #pragma unroll
        for (int j = 0; j < 8; j++) {
            const int col = n0 + wn*64 + j*8 + cc;
            float2 v0 = make_float2(acc[mi][j][0], acc[mi][j][1]);
            float2 v1 = make_float2(acc[mi][j][2], acc[mi][j][3]);
            *(float2*)(C + (size_t)(rowb + rr)     * N + col) = v0;
            *(float2*)(C + (size_t)(rowb + rr + 8) * N + col) = v1;
        }
    }
}

// ---------------- conversion: x -> bf16 split [hi|hi|lo] ----------------
__global__ __launch_bounds__(256) void convert_x_kernel(const float* __restrict__ x)
{
    const int idx = blockIdx.x * 256 + threadIdx.x;
    const int m  = idx >> 8;
    const int c4 = (idx & 255) * 4;
    float4 v = *(const float4*)(x + (size_t)m * D_ + c4);
    float vv[4] = {v.x, v.y, v.z, v.w};
    __nv_bfloat16 hi[4], lo[4];
    #pragma unroll
    for (int i = 0; i < 4; i++) {
        hi[i] = __float2bfloat16(vv[i]);
        lo[i] = __float2bfloat16(vv[i] - __bfloat162float(hi[i]));
    }
    __nv_bfloat16* dst = g_Ax + (size_t)m * KX + c4;
    *(uint2*)(dst)        = *(uint2*)hi;
    *(uint2*)(dst + 1024) = *(uint2*)hi;
    *(uint2*)(dst + 2048) = *(uint2*)lo;
}

// ------- conversion: all four W[K,N] -> Bt[N,3K] split [hi|lo|hi], z-grid ----
__global__ __launch_bounds__(1024) void convert_w_kernel(const float* __restrict__ Wq,
                                                         const float* __restrict__ Wk,
                                                         const float* __restrict__ Wv,
                                                         const float* __restrict__ Wo)
{
    __shared__ float t[32][33];
    const int z  = blockIdx.z;
    const float* W = (z == 0) ? Wq : ((z == 1) ? Wk : ((z == 2) ? Wv : Wo));
    __nv_bfloat16* Bt;
    if (z < 3) { Bt = g_Bqkv + (size_t)z * 1024 * KX; }
    else       { Bt = g_Bo; }

    const int tx = threadIdx.x & 31, ty = threadIdx.x >> 5;
    const int n0 = blockIdx.x * 32, k0 = blockIdx.y * 32;
    t[ty][tx] = W[(size_t)(k0 + ty) * D_ + n0 + tx];
    __syncthreads();
    const float v = t[tx][ty];   // = W[k0+tx][n0+ty]
    const __nv_bfloat16 hi = __float2bfloat16(v);
    const __nv_bfloat16 lo = __float2bfloat16(v - __bfloat162float(hi));
    __nv_bfloat16* dst = Bt + (size_t)(n0 + ty) * KX + k0 + tx;
    dst[0]    = hi;
    dst[1024] = lo;
    dst[2048] = hi;
}

// ---------------- K2: small projections, 32 tokens/block (grid=256) ---------
__global__ __launch_bounds__(256) void smallproj_kernel(const float* __restrict__ x,
                                                        const float* __restrict__ Wb,
                                                        const float* __restrict__ Wfd,
                                                        const float* __restrict__ bfd,
                                                        const float* __restrict__ Wsd,
                                                        const float* __restrict__ bsd)
{
    __shared__ float xs[32][65];
    __shared__ float ws[64][48];
    const int tid = threadIdx.x;
    const int m0  = blockIdx.x * 32;
    const int tok = tid & 31;
    const int og  = (tid >> 5) * 6;     // 8 groups x 6 outputs = 48

    float acc[6];
    #pragma unroll
    for (int j = 0; j < 6; j++) acc[j] = 0.0f;

    for (int k0 = 0; k0 < D_; k0 += 64) {
        for (int i = tid; i < 512; i += 256) {
            const int r = i >> 4, c = (i & 15) * 4;
            float4 v = *(const float4*)(x + (size_t)(m0 + r) * D_ + k0 + c);
            xs[r][c] = v.x; xs[r][c+1] = v.y; xs[r][c+2] = v.z; xs[r][c+3] = v.w;
        }
        for (int i = tid; i < 3072; i += 256) {
            const int k = i / 48, o = i % 48;
            const float* W = (o < 16) ? Wb : ((o < 32) ? Wfd : Wsd);
            ws[k][o] = W[(size_t)(k0 + k) * 16 + (o & 15)];
        }
        __syncthreads();
        #pragma unroll 8
        for (int k = 0; k < 64; k++) {
            const float xv = xs[tok][k];
            #pragma unroll
            for (int j = 0; j < 6; j++) acc[j] = fmaf(xv, ws[k][og + j], acc[j]);
        }
        __syncthreads();
    }

    const int m = m0 + tok;
    const int b = m >> 12;
    const int l = m & (L_-1);
    #pragma unroll
    for (int j = 0; j < 6; j++) {
        const int o = og + j;
        const int which = o >> 4, h = o & 15;
        const size_t idx = ((size_t)b*H_ + h)*L_ + l;
        if (which == 0)      g_beta[idx] = sigmoidf_(acc[j]);
        else if (which == 1) g_logf[idx] = logf(sigmoidf_(acc[j] + bfd[h]) + 1e-6f);
        else                 g_logs[idx] = logf(sigmoidf_(acc[j] + bsd[h]) + 1e-6f);
    }
}

// ---------------- K3: per-token prep ----------------
__global__ __launch_bounds__(128) void prep_kernel(const float* __restrict__ Wtf1,
                                                   const float* __restrict__ btf1,
                                                   const float* __restrict__ Wtf2,
                                                   const float* __restrict__ btf2)
{
    const int wip  = threadIdx.x >> 5;
    const int lane = threadIdx.x & 31;
    const size_t w = (size_t)blockIdx.x*4 + wip;
    const int bh = (int)(w / L_);
    const int l  = (int)(w % L_);
    const int b  = bh >> 4;
    const int h  = bh & 15;

    __shared__ float kbs[4][DK_];

    const size_t src = ((size_t)b*L_ + l)*(3*D_) + (size_t)h*DK_;
    float q0 = g_qkv[src + lane],          q1 = g_qkv[src + 32 + lane];
    float k0 = g_qkv[src + 1024 + lane],   k1 = g_qkv[src + 1024 + 32 + lane];
    float v0 = g_qkv[src + 2048 + lane],   v1 = g_qkv[src + 2048 + 32 + lane];

    float sq = q0*q0 + q1*q1;
    #pragma unroll
    for (int off = 16; off; off >>= 1) sq += __shfl_xor_sync(0xffffffffu, sq, off);
    float qinv = 1.0f / fmaxf(sqrtf(sq), 1e-12f);

    float sk = k0*k0 + k1*k1;
    #pragma unroll
    for (int off = 16; off; off >>= 1) sk += __shfl_xor_sync(0xffffffffu, sk, off);
    float kinv = 1.0f / fmaxf(sqrtf(sk), 1e-12f);

    const float beta = g_beta[(size_t)bh*L_ + l];
    const float kb0 = k0*kinv*beta, kb1 = k1*kinv*beta;

    const size_t dst = ((size_t)bh*L_ + l)*DK_;
    g_qn[dst + lane]      = q0*qinv;
    g_qn[dst + 32 + lane] = q1*qinv;
    g_kb[dst + lane]      = kb0;
    g_kb[dst + 32 + lane] = kb1;
    g_vs[dst + lane]      = v0*beta;
    g_vs[dst + 32 + lane] = v1*beta;

    kbs[wip][lane]      = kb0;
    kbs[wip][lane + 32] = kb1;
    __syncwarp();

    float hsum = btf1[lane];
    #pragma unroll 8
    for (int d = 0; d < DK_; d++) hsum = fmaf(kbs[wip][d], Wtf1[d*32 + lane], hsum);
    float sil = hsum / (1.0f + expf(-hsum));
    float acc = sil * Wtf2[lane];
    #pragma unroll
    for (int off = 16; off; off >>= 1) acc += __shfl_xor_sync(0xffffffffu, acc, off);

    if (lane == 0) {
        float tf = sigmoidf_(acc + btf2[0]);
        tf = fminf(fmaxf(tf, 0.01f), 0.99f);
        g_alpha[(size_t)bh*L_ + l] = 0.5f + 0.3f*tf;
    }
}

// ---------------- K4: per-(b,h) cumsum scan (double) ----------------
__global__ __launch_bounds__(256) void scan_kernel()
{
    const int bh  = blockIdx.x;
    const int tid = threadIdx.x;
    const int PER = L_ / 256;
    __shared__ double s[256];

    for (int fs = 0; fs < 2; fs++) {
        const float* lg = (fs == 0) ? g_logf : g_logs;
        float*       wv = (fs == 0) ? g_fw   : g_sw;

        double loc[16];
        double run = 0.0;
        const size_t base = (size_t)bh*L_ + (size_t)tid*PER;
        #pragma unroll
        for (int i = 0; i < PER; i++) { run += (double)lg[base + i]; loc[i] = run; }
        s[tid] = run;
        __syncthreads();
        for (int off = 1; off < 256; off <<= 1) {
            double v = (tid >= off) ? s[tid - off] : 0.0;
            __syncthreads();
            s[tid] += v;
            __syncthreads();
        }
        const double excl  = s[tid] - run;
        const double total = s[255];
        __syncthreads();

        double acc = 0.0;
        #pragma unroll
        for (int i = 0; i < PER; i++) {
            double ww = exp(total - (excl + loc[i]));
            wv[base + i] = (float)ww;
            acc += ww;
        }
        s[tid] = acc;
        __syncthreads();
        for (int off = 128; off > 0; off >>= 1) {
            if (tid < off) s[tid] += s[tid + off];
            __syncthreads();
        }
        if (tid == 0) g_wsum[bh*2 + fs] = (float)s[0];
        __syncthreads();
    }
}

// ---------------- K5: partial KV outer-product states (256 tok/chunk) -------
__global__ __launch_bounds__(256) void outer_kernel()
{
    const int bh  = blockIdx.y;
    const int ch  = blockIdx.x;        // 0..NCHUNK-1, each 256 tokens
    const int tid = threadIdx.x;
    __shared__ float ks [64*64];
    __shared__ float vsh[64*64];
    __shared__ float fsh[64], ssh[64];

    const int d0 = (tid >> 4) * 4;
    const int e0 = (tid & 15) * 4;
    float af[4][4], as_[4][4];
    #pragma unroll
    for (int i = 0; i < 4; i++)
        #pragma unroll
        for (int j = 0; j < 4; j++) { af[i][j] = 0.f; as_[i][j] = 0.f; }

    for (int sub = 0; sub < CHT/64; sub++) {
        const int l0 = ch * CHT + sub * 64;
        const float* kbp = g_kb + ((size_t)bh*L_ + l0)*DK_;
        const float* vsp = g_vs + ((size_t)bh*L_ + l0)*DK_;
        for (int i = tid*4; i < 4096; i += 1024) {
            *(float4*)(ks + i)  = *(const float4*)(kbp + i);
            *(float4*)(vsh + i) = *(const float4*)(vsp + i);
        }
        if (tid < 64) {
            fsh[tid] = g_fw[(size_t)bh*L_ + l0 + tid];
            ssh[tid] = g_sw[(size_t)bh*L_ + l0 + tid];
        }
        __syncthreads();

        for (int ll = 0; ll < 64; ll++) {
            const float f = fsh[ll], sdec = ssh[ll];
            float kd[4], ve[4];
            #pragma unroll
            for (int i = 0; i < 4; i++) kd[i] = ks[ll*64 + d0 + i];
            #pragma unroll
            for (int j = 0; j < 4; j++) ve[j] = vsh[ll*64 + e0 + j];
            #pragma unroll
            for (int i = 0; i < 4; i++) {
                const float kf = kd[i]*f, ksl = kd[i]*sdec;
                #pragma unroll
                for (int j = 0; j < 4; j++) {
                    af[i][j]  = fmaf(kf,  ve[j], af[i][j]);
                    as_[i][j] = fmaf(ksl, ve[j], as_[i][j]);
                }
            }
        }
        __syncthreads();
    }

    float* pf = g_part + ((size_t)(bh*NCHUNK + ch))*8192;
    #pragma unroll
    for (int i = 0; i < 4; i++)
        #pragma unroll
        for (int j = 0; j < 4; j++) {
            pf[(d0+i)*64 + e0 + j]        = af[i][j];
            pf[4096 + (d0+i)*64 + e0 + j] = as_[i][j];
        }
}

// ---------------- K6: reduce partials + normalize (grid 32x8) ----------------
__global__ __launch_bounds__(256) void reduce_kernel()
{
    const int bh  = blockIdx.x;
    const int seg = blockIdx.y;        // 8 segments of 1024
    const int idx = seg * 1024 + threadIdx.x * 4;
    const int fs  = idx >> 12;
    float4 sum = make_float4(0.f, 0.f, 0.f, 0.f);
    for (int c = 0; c < NCHUNK; c++) {
        float4 v = *(const float4*)(g_part + ((size_t)(bh*NCHUNK + c))*8192 + idx);
        sum.x += v.x; sum.y += v.y; sum.z += v.z; sum.w += v.w;
    }
    const float inv = 1.0f / (g_wsum[bh*2 + fs] + 1e-6f);
    sum.x *= inv; sum.y *= inv; sum.z *= inv; sum.w *= inv;
    *(float4*)(g_M + (size_t)bh*8192 + idx) = sum;
}

// ---------------- K7: output mix -> writes bf16 split A for final GEMM ------
__global__ __launch_bounds__(256) void outproj_kernel()
{
    const int bh  = blockIdx.y;
    const int lt  = blockIdx.x;
    const int tid = threadIdx.x;
    __shared__ float qs[32*64];
    __shared__ float Mf[64*64];
    __shared__ float Ms[64*64];
    __shared__ float al[32];

    const int l0 = lt * 32;
    const float* qp = g_qn + ((size_t)bh*L_ + l0)*DK_;
    for (int i = tid*4; i < 2048; i += 1024) *(float4*)(qs + i) = *(const float4*)(qp + i);
    const float* Mp = g_M + (size_t)bh*8192;
    for (int i = tid*4; i < 4096; i += 1024) {
        *(float4*)(Mf + i) = *(const float4*)(Mp + i);
        *(float4*)(Ms + i) = *(const float4*)(Mp + 4096 + i);
    }
    if (tid < 32) al[tid] = g_alpha[(size_t)bh*L_ + l0 + tid];
    __syncthreads();

    const int li = tid >> 3;
    const int e0 = (tid & 7) * 8;
    float of[8], os[8];
    #pragma unroll
    for (int j = 0; j < 8; j++) { of[j] = 0.f; os[j] = 0.f; }

    #pragma unroll 4
    for (int d = 0; d < 64; d++) {
        const float qv = qs[li*64 + d];
        #pragma unroll
        for (int j = 0; j < 8; j++) {
            of[j] = fmaf(qv, Mf[d*64 + e0 + j], of[j]);
            os[j] = fmaf(qv, Ms[d*64 + e0 + j], os[j]);
        }
    }
    const float a = al[li];
    const int b = bh >> 4, h = bh & 15;
    const size_t m = (size_t)b*L_ + l0 + li;
    __nv_bfloat16 hi[8], lo[8];
    #pragma unroll
    for (int j = 0; j < 8; j++) {
        const float val = a*of[j] + (1.0f - a)*os[j];
        hi[j] = __float2bfloat16(val);
        lo[j] = __float2bfloat16(val - __bfloat162float(hi[j]));
    }
    __nv_bfloat16* dst = g_Ao + m*KX + (size_t)h*DK_ + e0;
    *(uint4*)(dst)        = *(uint4*)hi;
    *(uint4*)(dst + 1024) = *(uint4*)hi;
    *(uint4*)(dst + 2048) = *(uint4*)lo;
}

// ---------------- launch ----------------
extern "C" void kernel_launch(void* const* d_in, const int* in_sizes, int n_in,
                              void* d_out, int out_size)
{
    const float* x    = (const float*)d_in[0];
    const float* Wq   = (const float*)d_in[1];
    const float* Wk   = (const float*)d_in[2];
    const float* Wv   = (const float*)d_in[3];
    const float* Wb   = (const float*)d_in[4];
    const float* Wo   = (const float*)d_in[5];
    const float* Wfd  = (const float*)d_in[6];
    const float* bfd  = (const float*)d_in[7];
    const float* Wsd  = (const float*)d_in[8];
    const float* bsd  = (const float*)d_in[9];
    const float* Wtf1 = (const float*)d_in[10];
    const float* btf1 = (const float*)d_in[11];
    const float* Wtf2 = (const float*)d_in[12];
    const float* btf2 = (const float*)d_in[13];
    float* out = (float*)d_out;

    __nv_bfloat16 *Ax, *Ao, *Bqkv, *Bo;
    float *qkv;
    cudaGetSymbolAddress((void**)&Ax,   g_Ax);
    cudaGetSymbolAddress((void**)&Ao,   g_Ao);
    cudaGetSymbolAddress((void**)&Bqkv, g_Bqkv);
    cudaGetSymbolAddress((void**)&Bo,   g_Bo);
    cudaGetSymbolAddress((void**)&qkv,  g_qkv);

    cudaFuncSetAttribute(gemm_bf16_mma, cudaFuncAttributeMaxDynamicSharedMemorySize, GSMEM);

    // conversions
    convert_x_kernel<<<(MROWS * D_ / 4) / 256, 256>>>(x);
    dim3 wgrid(D_/32, D_/32, 4);
    convert_w_kernel<<<wgrid, 1024>>>(Wq, Wk, Wv, Wo);

    // fused q|k|v GEMM: [8192, 3072] = Ax[8192,3072k] * Bqkv[3072n,3072k]^T
    dim3 qkvgrid(3*D_/128, MROWS/128);   // (24, 64)
    gemm_bf16_mma<<<qkvgrid, 256, GSMEM>>>(Ax, Bqkv, qkv, MROWS, 3*D_, KX);

    smallproj_kernel<<<MROWS/32, 256>>>(x, Wb, Wfd, bfd, Wsd, bsd);
    prep_kernel<<<(BH * L_) / 4, 128>>>(Wtf1, btf1, Wtf2, btf2);
    scan_kernel<<<BH, 256>>>();

    dim3 ogrid(NCHUNK, BH);                  // (16, 32)
    outer_kernel<<<ogrid, 256>>>();
    dim3 rgrid(BH, 8);
    reduce_kernel<<<rgrid, 256>>>();

    dim3 pgrid(L_ / 32, BH);
    outproj_kernel<<<pgrid, 256>>>();

    // final GEMM: out[8192,1024] = Ao[8192,3072k] * Bo[1024n,3072k]^T
    dim3 fgrid(D_/128, MROWS/128);       // (8, 64)
    gemm_bf16_mma<<<fgrid, 256, GSMEM>>>(Ao, Bo, out, MROWS, D_, KX);
}

// round 11
// speedup vs baseline: 1.2970x; 1.0794x over previous
#include <cuda_runtime.h>
#include <cuda_bf16.h>
#include <math.h>
#include <stdint.h>

// Problem constants
#define B_ 2
#define L_ 4096
#define D_ 1024
#define H_ 16
#define DK_ 64
#define MROWS (B_*L_)          // 8192
#define BH (B_*H_)             // 32
#define NCHUNK 16              // 256 tokens per partial chunk
#define CHT 256                // tokens per chunk
#define KX 3072                // expanded K (3x bf16 split)
#define NX 3200                // QKV GEMM N: 3072 qkv + 48 decay proj + 80 pad

// ---------------- scratch (device globals; allocation-free) ----------------
__device__ __align__(16) __nv_bfloat16 g_Ax  [MROWS*KX];   // x split  [M, 3072]  (hi|hi|lo)
__device__ __align__(16) __nv_bfloat16 g_Ao  [MROWS*KX];   // o split  [M, 3072]
__device__ __align__(16) __nv_bfloat16 g_Bqkv[NX*KX];      // Wq|Wk|Wv|Wb|Wfd|Wsd|0-pad [3200 N, 3072 K]
__device__ __align__(16) __nv_bfloat16 g_Bo  [D_*KX];      // Wo [1024 N, 3072 K]
__device__ float g_qkv[MROWS*NX];    // q|k|v|decay linear outputs [M, 3200]
__device__ float g_qn [MROWS*D_];    // [bh][l][dk]
__device__ float g_kb [MROWS*D_];
__device__ float g_vs [MROWS*D_];
__device__ float g_beta [BH*L_];
__device__ float g_logf [BH*L_];
__device__ float g_logs [BH*L_];
__device__ float g_fw   [BH*L_];
__device__ float g_sw   [BH*L_];
__device__ float g_alpha[BH*L_];
__device__ float g_wsum [BH*2];
__device__ float g_part [BH*NCHUNK*2*DK_*DK_];   // 4.2M floats
__device__ float g_M    [BH*2*DK_*DK_];

__device__ __forceinline__ float sigmoidf_(float x){ return 1.0f/(1.0f+expf(-x)); }

// ======================= PTX helpers (sm_80-compatible) =====================
__device__ __forceinline__ uint32_t smem_u32(const void* p){
    return (uint32_t)__cvta_generic_to_shared(p);
}
__device__ __forceinline__ void cp_async16(uint32_t saddr, const void* gaddr){
    asm volatile("cp.async.cg.shared.global [%0], [%1], 16;" :: "r"(saddr), "l"(gaddr));
}
__device__ __forceinline__ void cp_commit(){ asm volatile("cp.async.commit_group;"); }
#define CP_WAIT(n) asm volatile("cp.async.wait_group %0;" :: "n"(n))

__device__ __forceinline__ void ldmat_x4(uint32_t* r, uint32_t addr){
    asm volatile("ldmatrix.sync.aligned.m8n8.x4.shared.b16 {%0,%1,%2,%3}, [%4];"
        : "=r"(r[0]), "=r"(r[1]), "=r"(r[2]), "=r"(r[3]) : "r"(addr));
}
__device__ __forceinline__ void mma16816(float* c, const uint32_t* a, uint32_t b0, uint32_t b1){
    asm volatile("mma.sync.aligned.m16n8k16.row.col.f32.bf16.bf16.f32 "
        "{%0,%1,%2,%3}, {%4,%5,%6,%7}, {%8,%9}, {%0,%1,%2,%3};"
        : "+f"(c[0]), "+f"(c[1]), "+f"(c[2]), "+f"(c[3])
        : "r"(a[0]), "r"(a[1]), "r"(a[2]), "r"(a[3]), "r"(b0), "r"(b1));
}

// ====== HMMA bf16 GEMM: C[M,N] = A[M,K] * B[N,K]^T (both row-major, bf16) ===
// Block tile 128x128, K-chunk 32, 4-stage cp.async pipeline, 2 CTAs/SM.
#define BKC 32
#define SSTR 40                        // smem row stride in bf16 (80B, conflict-free)
#define HTILE (128*SSTR*2)             // 10240 B (one operand per stage)
#define STG (2*HTILE)                  // 20480 B per stage (A+B)
#define NST 4
#define GSMEM (NST*STG)                // 81920 B

__global__ __launch_bounds__(256, 2)
void gemm_bf16_mma(const __nv_bfloat16* __restrict__ A,
                   const __nv_bfloat16* __restrict__ B,
                   float* __restrict__ C, int M, int N, int K)
{
    extern __shared__ char sm[];
    const uint32_t sbase = smem_u32(sm);
    const int tid  = threadIdx.x;
    const int wid  = tid >> 5;
    const int lane = tid & 31;
    const int wm   = wid & 3;
    const int wn   = wid >> 2;

    const int m0 = blockIdx.y * 128;
    const int n0 = blockIdx.x * 128;
    const __nv_bfloat16* Ag = A + (size_t)m0 * K;
    const __nv_bfloat16* Bg = B + (size_t)n0 * K;

    const int r0s = tid >> 2;
    const int r1s = r0s + 64;
    const int cs  = (tid & 3) * 8;
    const uint32_t oA0 = (uint32_t)(r0s * SSTR + cs) * 2;
    const uint32_t oA1 = (uint32_t)(r1s * SSTR + cs) * 2;
    const uint32_t oB0 = HTILE + oA0;
    const uint32_t oB1 = HTILE + oA1;

    const int arow = (lane & 15);
    const int akof = (lane >> 4) * 8;
    uint32_t aoff[2];
    #pragma unroll
    for (int mi = 0; mi < 2; mi++)
        aoff[mi] = (uint32_t)((wm*32 + mi*16 + arow) * SSTR + akof) * 2;

    const int brow = (lane & 7) + ((lane >> 4) << 3);
    const int bkof = ((lane >> 3) & 1) * 8;
    uint32_t boff[4];
    #pragma unroll
    for (int ni = 0; ni < 4; ni++)
        boff[ni] = HTILE + (uint32_t)((wn*64 + ni*16 + brow) * SSTR + bkof) * 2;

    float acc[2][8][4];
    #pragma unroll
    for (int mi = 0; mi < 2; mi++)
        #pragma unroll
        for (int j = 0; j < 8; j++)
            #pragma unroll
            for (int t = 0; t < 4; t++) acc[mi][j][t] = 0.0f;

    const int nch = K / BKC;

    #pragma unroll
    for (int s = 0; s < NST - 1; s++) {
        const size_t kc = (size_t)s * BKC;
        const uint32_t sa = sbase + s * STG;
        cp_async16(sa + oA0, Ag + (size_t)r0s * K + kc + cs);
        cp_async16(sa + oA1, Ag + (size_t)r1s * K + kc + cs);
        cp_async16(sa + oB0, Bg + (size_t)r0s * K + kc + cs);
        cp_async16(sa + oB1, Bg + (size_t)r1s * K + kc + cs);
        cp_commit();
    }

    for (int c = 0; c < nch; c++) {
        CP_WAIT(NST - 2);
        __syncthreads();

        {
            const int cn = c + NST - 1;
            if (cn < nch) {
                const size_t kc = (size_t)cn * BKC;
                const uint32_t sa = sbase + (uint32_t)(cn & (NST - 1)) * STG;
                cp_async16(sa + oA0, Ag + (size_t)r0s * K + kc + cs);
                cp_async16(sa + oA1, Ag + (size_t)r1s * K + kc + cs);
                cp_async16(sa + oB0, Bg + (size_t)r0s * K + kc + cs);
                cp_async16(sa + oB1, Bg + (size_t)r1s * K + kc + cs);
            }
            cp_commit();
        }

        const uint32_t so = sbase + (uint32_t)(c & (NST - 1)) * STG;
        #pragma unroll
        for (int kk = 0; kk < 2; kk++) {
            const uint32_t ko = (uint32_t)(kk * 16) * 2;
            uint32_t a[2][4];
            #pragma unroll
            for (int mi = 0; mi < 2; mi++) ldmat_x4(a[mi], so + aoff[mi] + ko);
            uint32_t bf[4][4];
            #pragma unroll
            for (int ni = 0; ni < 4; ni++) ldmat_x4(bf[ni], so + boff[ni] + ko);
            #pragma unroll
            for (int mi = 0; mi < 2; mi++)
                #pragma unroll
                for (int ni = 0; ni < 4; ni++) {
                    mma16816(acc[mi][ni*2+0], a[mi], bf[ni][0], bf[ni][1]);
                    mma16816(acc[mi][ni*2+1], a[mi], bf[ni][2], bf[ni][3]);
                }
        }
    }

    const int rr = lane >> 2;
    const int cc = (lane & 3) * 2;
    #pragma unroll
    for (int mi = 0; mi < 2; mi++) {
        const int rowb = m0 + wm*32 + mi*16;
        #pragma unroll
        for (int j = 0; j < 8; j++) {
            const int col = n0 + wn*64 + j*8 + cc;
            float2 v0 = make_float2(acc[mi][j][0], acc[mi][j][1]);
            float2 v1 = make_float2(acc[mi][j][2], acc[mi][j][3]);
            *(float2*)(C + (size_t)(rowb + rr)     * N + col) = v0;
            *(float2*)(C + (size_t)(rowb + rr + 8) * N + col) = v1;
        }
    }
}

// ---------------- conversion: x -> bf16 split [hi|hi|lo] ----------------
__global__ __launch_bounds__(256) void convert_x_kernel(const float* __restrict__ x)
{
    const int idx = blockIdx.x * 256 + threadIdx.x;
    const int m  = idx >> 8;
    const int c4 = (idx & 255) * 4;
    float4 v = *(const float4*)(x + (size_t)m * D_ + c4);
    float vv[4] = {v.x, v.y, v.z, v.w};
    __nv_bfloat16 hi[4], lo[4];
    #pragma unroll
    for (int i = 0; i < 4; i++) {
        hi[i] = __float2bfloat16(vv[i]);
        lo[i] = __float2bfloat16(vv[i] - __bfloat162float(hi[i]));
    }
    __nv_bfloat16* dst = g_Ax + (size_t)m * KX + c4;
    *(uint2*)(dst)        = *(uint2*)hi;
    *(uint2*)(dst + 1024) = *(uint2*)hi;
    *(uint2*)(dst + 2048) = *(uint2*)lo;
}

// ------- conversion: all four W[K,N] -> Bt[N,3K] split [hi|lo|hi], z-grid ----
__global__ __launch_bounds__(1024) void convert_w_kernel(const float* __restrict__ Wq,
                                                         const float* __restrict__ Wk,
                                                         const float* __restrict__ Wv,
                                                         const float* __restrict__ Wo)
{
    __shared__ float t[32][33];
    const int z  = blockIdx.z;
    const float* W = (z == 0) ? Wq : ((z == 1) ? Wk : ((z == 2) ? Wv : Wo));
    __nv_bfloat16* Bt;
    if (z < 3) { Bt = g_Bqkv + (size_t)z * 1024 * KX; }
    else       { Bt = g_Bo; }

    const int tx = threadIdx.x & 31, ty = threadIdx.x >> 5;
    const int n0 = blockIdx.x * 32, k0 = blockIdx.y * 32;
    t[ty][tx] = W[(size_t)(k0 + ty) * D_ + n0 + tx];
    __syncthreads();
    const float v = t[tx][ty];   // = W[k0+tx][n0+ty]
    const __nv_bfloat16 hi = __float2bfloat16(v);
    const __nv_bfloat16 lo = __float2bfloat16(v - __bfloat162float(hi));
    __nv_bfloat16* dst = Bt + (size_t)(n0 + ty) * KX + k0 + tx;
    dst[0]    = hi;
    dst[1024] = lo;
    dst[2048] = hi;
}

// ------- conversion: Wb|Wfd|Wsd [1024,16] -> g_Bqkv rows 3072..3119 ----------
__global__ __launch_bounds__(256) void convert_small_w_kernel(const float* __restrict__ Wb,
                                                              const float* __restrict__ Wfd,
                                                              const float* __restrict__ Wsd)
{
    const int gid = blockIdx.x * 256 + threadIdx.x;   // 48*1024 = 49152
    const int o = gid >> 10;      // 0..47
    const int k = gid & 1023;
    const float* W = (o < 16) ? Wb : ((o < 32) ? Wfd : Wsd);
    const float v = W[(size_t)k * 16 + (o & 15)];
    const __nv_bfloat16 hi = __float2bfloat16(v);
    const __nv_bfloat16 lo = __float2bfloat16(v - __bfloat162float(hi));
    __nv_bfloat16* dst = g_Bqkv + (size_t)(3072 + o) * KX + k;
    dst[0]    = hi;
    dst[1024] = lo;
    dst[2048] = hi;
}

// ---------------- K2': decay/beta from GEMM columns 3072..3119 --------------
__global__ __launch_bounds__(256) void decay_kernel(const float* __restrict__ bfd,
                                                    const float* __restrict__ bsd)
{
    const int gid = blockIdx.x * 256 + threadIdx.x;   // 8192*48
    const int m = gid / 48;
    const int o = gid % 48;
    const float acc = g_qkv[(size_t)m * NX + 3072 + o];
    const int b = m >> 12;
    const int l = m & (L_-1);
    const int which = o >> 4, h = o & 15;
    const size_t idx = ((size_t)b*H_ + h)*L_ + l;
    if (which == 0)      g_beta[idx] = sigmoidf_(acc);
    else if (which == 1) g_logf[idx] = logf(sigmoidf_(acc + bfd[h]) + 1e-6f);
    else                 g_logs[idx] = logf(sigmoidf_(acc + bsd[h]) + 1e-6f);
}

// ---------------- K3: per-token prep ----------------
__global__ __launch_bounds__(128) void prep_kernel(const float* __restrict__ Wtf1,
                                                   const float* __restrict__ btf1,
                                                   const float* __restrict__ Wtf2,
                                                   const float* __restrict__ btf2)
{
    const int wip  = threadIdx.x >> 5;
    const int lane = threadIdx.x & 31;
    const size_t w = (size_t)blockIdx.x*4 + wip;
    const int bh = (int)(w / L_);
    const int l  = (int)(w % L_);
    const int b  = bh >> 4;
    const int h  = bh & 15;

    __shared__ float kbs[4][DK_];

    const size_t src = ((size_t)b*L_ + l)*NX + (size_t)h*DK_;
    float q0 = g_qkv[src + lane],          q1 = g_qkv[src + 32 + lane];
    float k0 = g_qkv[src + 1024 + lane],   k1 = g_qkv[src + 1024 + 32 + lane];
    float v0 = g_qkv[src + 2048 + lane],   v1 = g_qkv[src + 2048 + 32 + lane];

    float sq = q0*q0 + q1*q1;
    #pragma unroll
    for (int off = 16; off; off >>= 1) sq += __shfl_xor_sync(0xffffffffu, sq, off);
    float qinv = 1.0f / fmaxf(sqrtf(sq), 1e-12f);

    float sk = k0*k0 + k1*k1;
    #pragma unroll
    for (int off = 16; off; off >>= 1) sk += __shfl_xor_sync(0xffffffffu, sk, off);
    float kinv = 1.0f / fmaxf(sqrtf(sk), 1e-12f);

    const float beta = g_beta[(size_t)bh*L_ + l];
    const float kb0 = k0*kinv*beta, kb1 = k1*kinv*beta;

    const size_t dst = ((size_t)bh*L_ + l)*DK_;
    g_qn[dst + lane]      = q0*qinv;
    g_qn[dst + 32 + lane] = q1*qinv;
    g_kb[dst + lane]      = kb0;
    g_kb[dst + 32 + lane] = kb1;
    g_vs[dst + lane]      = v0*beta;
    g_vs[dst + 32 + lane] = v1*beta;

    kbs[wip][lane]      = kb0;
    kbs[wip][lane + 32] = kb1;
    __syncwarp();

    float hsum = btf1[lane];
    #pragma unroll 8
    for (int d = 0; d < DK_; d++) hsum = fmaf(kbs[wip][d], Wtf1[d*32 + lane], hsum);
    float sil = hsum / (1.0f + expf(-hsum));
    float acc = sil * Wtf2[lane];
    #pragma unroll
    for (int off = 16; off; off >>= 1) acc += __shfl_xor_sync(0xffffffffu, acc, off);

    if (lane == 0) {
        float tf = sigmoidf_(acc + btf2[0]);
        tf = fminf(fmaxf(tf, 0.01f), 0.99f);
        g_alpha[(size_t)bh*L_ + l] = 0.5f + 0.3f*tf;
    }
}

// ---------------- K4: per-(b,h) cumsum scan (double) ----------------
__global__ __launch_bounds__(256) void scan_kernel()
{
    const int bh  = blockIdx.x;
    const int tid = threadIdx.x;
    const int PER = L_ / 256;
    __shared__ double s[256];

    for (int fs = 0; fs < 2; fs++) {
        const float* lg = (fs == 0) ? g_logf : g_logs;
        float*       wv = (fs == 0) ? g_fw   : g_sw;

        double loc[16];
        double run = 0.0;
        const size_t base = (size_t)bh*L_ + (size_t)tid*PER;
        #pragma unroll
        for (int i = 0; i < PER; i++) { run += (double)lg[base + i]; loc[i] = run; }
        s[tid] = run;
        __syncthreads();
        for (int off = 1; off < 256; off <<= 1) {
            double v = (tid >= off) ? s[tid - off] : 0.0;
            __syncthreads();
            s[tid] += v;
            __syncthreads();
        }
        const double excl  = s[tid] - run;
        const double total = s[255];
        __syncthreads();

        double acc = 0.0;
        #pragma unroll
        for (int i = 0; i < PER; i++) {
            double ww = exp(total - (excl + loc[i]));
            wv[base + i] = (float)ww;
            acc += ww;
        }
        s[tid] = acc;
        __syncthreads();
        for (int off = 128; off > 0; off >>= 1) {
            if (tid < off) s[tid] += s[tid + off];
            __syncthreads();
        }
        if (tid == 0) g_wsum[bh*2 + fs] = (float)s[0];
        __syncthreads();
    }
}

// ---------------- K5: partial KV outer-product states (256 tok/chunk) -------
__global__ __launch_bounds__(256) void outer_kernel()
{
    const int bh  = blockIdx.y;
    const int ch  = blockIdx.x;
    const int tid = threadIdx.x;
    __shared__ float ks [64*64];
    __shared__ float vsh[64*64];
    __shared__ float fsh[64], ssh[64];

    const int d0 = (tid >> 4) * 4;
    const int e0 = (tid & 15) * 4;
    float af[4][4], as_[4][4];
    #pragma unroll
    for (int i = 0; i < 4; i++)
        #pragma unroll
        for (int j = 0; j < 4; j++) { af[i][j] = 0.f; as_[i][j] = 0.f; }

    for (int sub = 0; sub < CHT/64; sub++) {
        const int l0 = ch * CHT + sub * 64;
        const float* kbp = g_kb + ((size_t)bh*L_ + l0)*DK_;
        const float* vsp = g_vs + ((size_t)bh*L_ + l0)*DK_;
        for (int i = tid*4; i < 4096; i += 1024) {
            *(float4*)(ks + i)  = *(const float4*)(kbp + i);
            *(float4*)(vsh + i) = *(const float4*)(vsp + i);
        }
        if (tid < 64) {
            fsh[tid] = g_fw[(size_t)bh*L_ + l0 + tid];
            ssh[tid] = g_sw[(size_t)bh*L_ + l0 + tid];
        }
        __syncthreads();

        for (int ll = 0; ll < 64; ll++) {
            const float f = fsh[ll], sdec = ssh[ll];
            float kd[4], ve[4];
            #pragma unroll
            for (int i = 0; i < 4; i++) kd[i] = ks[ll*64 + d0 + i];
            #pragma unroll
            for (int j = 0; j < 4; j++) ve[j] = vsh[ll*64 + e0 + j];
            #pragma unroll
            for (int i = 0; i < 4; i++) {
                const float kf = kd[i]*f, ksl = kd[i]*sdec;
                #pragma unroll
                for (int j = 0; j < 4; j++) {
                    af[i][j]  = fmaf(kf,  ve[j], af[i][j]);
                    as_[i][j] = fmaf(ksl, ve[j], as_[i][j]);
                }
            }
        }
        __syncthreads();
    }

    float* pf = g_part + ((size_t)(bh*NCHUNK + ch))*8192;
    #pragma unroll
    for (int i = 0; i < 4; i++)
        #pragma unroll
        for (int j = 0; j < 4; j++) {
            pf[(d0+i)*64 + e0 + j]        = af[i][j];
            pf[4096 + (d0+i)*64 + e0 + j] = as_[i][j];
        }
}

// ---------------- K6: reduce partials + normalize (grid 32x8) ----------------
__global__ __launch_bounds__(256) void reduce_kernel()
{
    const int bh  = blockIdx.x;
    const int seg = blockIdx.y;
    const int idx = seg * 1024 + threadIdx.x * 4;
    const int fs  = idx >> 12;
    float4 sum = make_float4(0.f, 0.f, 0.f, 0.f);
    for (int c = 0; c < NCHUNK; c++) {
        float4 v = *(const float4*)(g_part + ((size_t)(bh*NCHUNK + c))*8192 + idx);
        sum.x += v.x; sum.y += v.y; sum.z += v.z; sum.w += v.w;
    }
    const float inv = 1.0f / (g_wsum[bh*2 + fs] + 1e-6f);
    sum.x *= inv; sum.y *= inv; sum.z *= inv; sum.w *= inv;
    *(float4*)(g_M + (size_t)bh*8192 + idx) = sum;
}

// ---------------- K7: output mix -> writes bf16 split A for final GEMM ------
__global__ __launch_bounds__(256) void outproj_kernel()
{
    const int bh  = blockIdx.y;
    const int lt  = blockIdx.x;
    const int tid = threadIdx.x;
    __shared__ float qs[32*64];
    __shared__ float Mf[64*64];
    __shared__ float Ms[64*64];
    __shared__ float al[32];

    const int l0 = lt * 32;
    const float* qp = g_qn + ((size_t)bh*L_ + l0)*DK_;
    for (int i = tid*4; i < 2048; i += 1024) *(float4*)(qs + i) = *(const float4*)(qp + i);
    const float* Mp = g_M + (size_t)bh*8192;
    for (int i = tid*4; i < 4096; i += 1024) {
        *(float4*)(Mf + i) = *(const float4*)(Mp + i);
        *(float4*)(Ms + i) = *(const float4*)(Mp + 4096 + i);
    }
    if (tid < 32) al[tid] = g_alpha[(size_t)bh*L_ + l0 + tid];
    __syncthreads();

    const int li = tid >> 3;
    const int e0 = (tid & 7) * 8;
    float of[8], os[8];
    #pragma unroll
    for (int j = 0; j < 8; j++) { of[j] = 0.f; os[j] = 0.f; }

    #pragma unroll 4
    for (int d = 0; d < 64; d++) {
        const float qv = qs[li*64 + d];
        #pragma unroll
        for (int j = 0; j < 8; j++) {
            of[j] = fmaf(qv, Mf[d*64 + e0 + j], of[j]);
            os[j] = fmaf(qv, Ms[d*64 + e0 + j], os[j]);
        }
    }
    const float a = al[li];
    const int b = bh >> 4, h = bh & 15;
    const size_t m = (size_t)b*L_ + l0 + li;
    __nv_bfloat16 hi[8], lo[8];
    #pragma unroll
    for (int j = 0; j < 8; j++) {
        const float val = a*of[j] + (1.0f - a)*os[j];
        hi[j] = __float2bfloat16(val);
        lo[j] = __float2bfloat16(val - __bfloat162float(hi[j]));
    }
    __nv_bfloat16* dst = g_Ao + m*KX + (size_t)h*DK_ + e0;
    *(uint4*)(dst)        = *(uint4*)hi;
    *(uint4*)(dst + 1024) = *(uint4*)hi;
    *(uint4*)(dst + 2048) = *(uint4*)lo;
}

// ---------------- launch ----------------
extern "C" void kernel_launch(void* const* d_in, const int* in_sizes, int n_in,
                              void* d_out, int out_size)
{
    const float* x    = (const float*)d_in[0];
    const float* Wq   = (const float*)d_in[1];
    const float* Wk   = (const float*)d_in[2];
    const float* Wv   = (const float*)d_in[3];
    const float* Wb   = (const float*)d_in[4];
    const float* Wo   = (const float*)d_in[5];
    const float* Wfd  = (const float*)d_in[6];
    const float* bfd  = (const float*)d_in[7];
    const float* Wsd  = (const float*)d_in[8];
    const float* bsd  = (const float*)d_in[9];
    const float* Wtf1 = (const float*)d_in[10];
    const float* btf1 = (const float*)d_in[11];
    const float* Wtf2 = (const float*)d_in[12];
    const float* btf2 = (const float*)d_in[13];
    float* out = (float*)d_out;

    __nv_bfloat16 *Ax, *Ao, *Bqkv, *Bo;
    float *qkv;
    cudaGetSymbolAddress((void**)&Ax,   g_Ax);
    cudaGetSymbolAddress((void**)&Ao,   g_Ao);
    cudaGetSymbolAddress((void**)&Bqkv, g_Bqkv);
    cudaGetSymbolAddress((void**)&Bo,   g_Bo);
    cudaGetSymbolAddress((void**)&qkv,  g_qkv);

    cudaFuncSetAttribute(gemm_bf16_mma, cudaFuncAttributeMaxDynamicSharedMemorySize, GSMEM);

    // conversions
    convert_x_kernel<<<(MROWS * D_ / 4) / 256, 256>>>(x);
    dim3 wgrid(D_/32, D_/32, 4);
    convert_w_kernel<<<wgrid, 1024>>>(Wq, Wk, Wv, Wo);
    convert_small_w_kernel<<<(48*1024)/256, 256>>>(Wb, Wfd, Wsd);

    // fused q|k|v|decay GEMM: [8192, 3200] = Ax[8192,3072k] * Bqkv[3200n,3072k]^T
    dim3 qkvgrid(NX/128, MROWS/128);     // (25, 64)
    gemm_bf16_mma<<<qkvgrid, 256, GSMEM>>>(Ax, Bqkv, qkv, MROWS, NX, KX);

    decay_kernel<<<(MROWS*48)/256, 256>>>(bfd, bsd);
    prep_kernel<<<(BH * L_) / 4, 128>>>(Wtf1, btf1, Wtf2, btf2);
    scan_kernel<<<BH, 256>>>();

    dim3 ogrid(NCHUNK, BH);                  // (16, 32)
    outer_kernel<<<ogrid, 256>>>();
    dim3 rgrid(BH, 8);
    reduce_kernel<<<rgrid, 256>>>();

    dim3 pgrid(L_ / 32, BH);
    outproj_kernel<<<pgrid, 256>>>();

    // final GEMM: out[8192,1024] = Ao[8192,3072k] * Bo[1024n,3072k]^T
    dim3 fgrid(D_/128, MROWS/128);       // (8, 64)
    gemm_bf16_mma<<<fgrid, 256, GSMEM>>>(Ao, Bo, out, MROWS, D_, KX);
}

// round 12
// speedup vs baseline: 1.3138x; 1.0130x over previous
#include <cuda_runtime.h>
#include <cuda_bf16.h>
#include <math.h>
#include <stdint.h>

// Problem constants
#define B_ 2
#define L_ 4096
#define D_ 1024
#define H_ 16
#define DK_ 64
#define MROWS (B_*L_)          // 8192
#define BH (B_*H_)             // 32
#define NCHUNK 16              // 256 tokens per partial chunk
#define CHT 256                // tokens per chunk
#define KX 3072                // expanded K (3x bf16 split)
#define NX 3200                // QKV GEMM N: 3072 qkv + 48 decay proj + 80 pad

// ---------------- scratch (device globals; allocation-free) ----------------
__device__ __align__(16) __nv_bfloat16 g_Ax  [MROWS*KX];   // x split  [M, 3072]  (hi|hi|lo)
__device__ __align__(16) __nv_bfloat16 g_Ao  [MROWS*KX];   // o split  [M, 3072]
__device__ __align__(16) __nv_bfloat16 g_Bqkv[NX*KX];      // Wq|Wk|Wv|Wb|Wfd|Wsd|0-pad [3200 N, 3072 K]
__device__ __align__(16) __nv_bfloat16 g_Bo  [D_*KX];      // Wo [1024 N, 3072 K]
__device__ float g_qkv[MROWS*NX];    // q|k|v|decay linear outputs [M, 3200]
__device__ float g_qn [MROWS*D_];    // [bh][l][dk]
__device__ float g_kb [MROWS*D_];
__device__ float g_vs [MROWS*D_];
__device__ float g_beta [BH*L_];
__device__ float g_logf [BH*L_];
__device__ float g_logs [BH*L_];
__device__ float g_fw   [BH*L_];
__device__ float g_sw   [BH*L_];
__device__ float g_alpha[BH*L_];
__device__ float g_wsum [BH*2];
__device__ float g_part [BH*NCHUNK*2*DK_*DK_];   // 4.2M floats
__device__ float g_M    [BH*2*DK_*DK_];

__device__ __forceinline__ float sigmoidf_(float x){ return 1.0f/(1.0f+expf(-x)); }

// ======================= PTX helpers (sm_80-compatible) =====================
__device__ __forceinline__ uint32_t smem_u32(const void* p){
    return (uint32_t)__cvta_generic_to_shared(p);
}
__device__ __forceinline__ void cp_async16(uint32_t saddr, const void* gaddr){
    asm volatile("cp.async.cg.shared.global [%0], [%1], 16;" :: "r"(saddr), "l"(gaddr));
}
__device__ __forceinline__ void cp_commit(){ asm volatile("cp.async.commit_group;"); }
#define CP_WAIT(n) asm volatile("cp.async.wait_group %0;" :: "n"(n))

__device__ __forceinline__ void ldmat_x4(uint32_t* r, uint32_t addr){
    asm volatile("ldmatrix.sync.aligned.m8n8.x4.shared.b16 {%0,%1,%2,%3}, [%4];"
        : "=r"(r[0]), "=r"(r[1]), "=r"(r[2]), "=r"(r[3]) : "r"(addr));
}
__device__ __forceinline__ void mma16816(float* c, const uint32_t* a, uint32_t b0, uint32_t b1){
    asm volatile("mma.sync.aligned.m16n8k16.row.col.f32.bf16.bf16.f32 "
        "{%0,%1,%2,%3}, {%4,%5,%6,%7}, {%8,%9}, {%0,%1,%2,%3};"
        : "+f"(c[0]), "+f"(c[1]), "+f"(c[2]), "+f"(c[3])
        : "r"(a[0]), "r"(a[1]), "r"(a[2]), "r"(a[3]), "r"(b0), "r"(b1));
}

// ====== HMMA bf16 GEMM: C[M,N] = A[M,K] * B[N,K]^T (both row-major, bf16) ===
// Block tile 128x128, K-chunk 32, 4-stage cp.async pipeline, 2 CTAs/SM.
// All 12 fragment loads for a chunk issued back-to-back before any MMA.
#define BKC 32
#define SSTR 40                        // smem row stride in bf16 (80B, conflict-free)
#define HTILE (128*SSTR*2)             // 10240 B (one operand per stage)
#define STG (2*HTILE)                  // 20480 B per stage (A+B)
#define NST 4
#define GSMEM (NST*STG)                // 81920 B

__global__ __launch_bounds__(256, 2)
void gemm_bf16_mma(const __nv_bfloat16* __restrict__ A,
                   const __nv_bfloat16* __restrict__ B,
                   float* __restrict__ C, int M, int N, int K)
{
    extern __shared__ char sm[];
    const uint32_t sbase = smem_u32(sm);
    const int tid  = threadIdx.x;
    const int wid  = tid >> 5;
    const int lane = tid & 31;
    const int wm   = wid & 3;
    const int wn   = wid >> 2;

    const int m0 = blockIdx.y * 128;
    const int n0 = blockIdx.x * 128;
    const __nv_bfloat16* Ag = A + (size_t)m0 * K;
    const __nv_bfloat16* Bg = B + (size_t)n0 * K;

    const int r0s = tid >> 2;
    const int r1s = r0s + 64;
    const int cs  = (tid & 3) * 8;
    const uint32_t oA0 = (uint32_t)(r0s * SSTR + cs) * 2;
    const uint32_t oA1 = (uint32_t)(r1s * SSTR + cs) * 2;
    const uint32_t oB0 = HTILE + oA0;
    const uint32_t oB1 = HTILE + oA1;

    const int arow = (lane & 15);
    const int akof = (lane >> 4) * 8;
    uint32_t aoff[2];
    #pragma unroll
    for (int mi = 0; mi < 2; mi++)
        aoff[mi] = (uint32_t)((wm*32 + mi*16 + arow) * SSTR + akof) * 2;

    const int brow = (lane & 7) + ((lane >> 4) << 3);
    const int bkof = ((lane >> 3) & 1) * 8;
    uint32_t boff[4];
    #pragma unroll
    for (int ni = 0; ni < 4; ni++)
        boff[ni] = HTILE + (uint32_t)((wn*64 + ni*16 + brow) * SSTR + bkof) * 2;

    float acc[2][8][4];
    #pragma unroll
    for (int mi = 0; mi < 2; mi++)
        #pragma unroll
        for (int j = 0; j < 8; j++)
            #pragma unroll
            for (int t = 0; t < 4; t++) acc[mi][j][t] = 0.0f;

    const int nch = K / BKC;

    #pragma unroll
    for (int s = 0; s < NST - 1; s++) {
        const size_t kc = (size_t)s * BKC;
        const uint32_t sa = sbase + s * STG;
        cp_async16(sa + oA0, Ag + (size_t)r0s * K + kc + cs);
        cp_async16(sa + oA1, Ag + (size_t)r1s * K + kc + cs);
        cp_async16(sa + oB0, Bg + (size_t)r0s * K + kc + cs);
        cp_async16(sa + oB1, Bg + (size_t)r1s * K + kc + cs);
        cp_commit();
    }

    for (int c = 0; c < nch; c++) {
        CP_WAIT(NST - 2);
        __syncthreads();

        {
            const int cn = c + NST - 1;
            if (cn < nch) {
                const size_t kc = (size_t)cn * BKC;
                const uint32_t sa = sbase + (uint32_t)(cn & (NST - 1)) * STG;
                cp_async16(sa + oA0, Ag + (size_t)r0s * K + kc + cs);
                cp_async16(sa + oA1, Ag + (size_t)r1s * K + kc + cs);
                cp_async16(sa + oB0, Bg + (size_t)r0s * K + kc + cs);
                cp_async16(sa + oB1, Bg + (size_t)r1s * K + kc + cs);
            }
            cp_commit();
        }

        const uint32_t so = sbase + (uint32_t)(c & (NST - 1)) * STG;

        // issue ALL fragment loads for the chunk back-to-back (LSU pipelines),
        // then run all 64 MMAs with no intra-chunk scoreboard stalls
        uint32_t a[2][2][4];
        uint32_t bf[2][4][4];
        #pragma unroll
        for (int kk = 0; kk < 2; kk++) {
            const uint32_t ko = (uint32_t)(kk * 16) * 2;
            #pragma unroll
            for (int mi = 0; mi < 2; mi++) ldmat_x4(a[kk][mi], so + aoff[mi] + ko);
            #pragma unroll
            for (int ni = 0; ni < 4; ni++) ldmat_x4(bf[kk][ni], so + boff[ni] + ko);
        }
        #pragma unroll
        for (int kk = 0; kk < 2; kk++)
            #pragma unroll
            for (int mi = 0; mi < 2; mi++)
                #pragma unroll
                for (int ni = 0; ni < 4; ni++) {
                    mma16816(acc[mi][ni*2+0], a[kk][mi], bf[kk][ni][0], bf[kk][ni][1]);
                    mma16816(acc[mi][ni*2+1], a[kk][mi], bf[kk][ni][2], bf[kk][ni][3]);
                }
    }

    const int rr = lane >> 2;
    const int cc = (lane & 3) * 2;
    #pragma unroll
    for (int mi = 0; mi < 2; mi++) {
        const int rowb = m0 + wm*32 + mi*16;
        #pragma unroll
        for (int j = 0; j < 8; j++) {
            const int col = n0 + wn*64 + j*8 + cc;
            float2 v0 = make_float2(acc[mi][j][0], acc[mi][j][1]);
            float2 v1 = make_float2(acc[mi][j][2], acc[mi][j][3]);
            *(float2*)(C + (size_t)(rowb + rr)     * N + col) = v0;
            *(float2*)(C + (size_t)(rowb + rr + 8) * N + col) = v1;
        }
    }
}

// ---------------- conversion: x -> bf16 split [hi|hi|lo] ----------------
__global__ __launch_bounds__(256) void convert_x_kernel(const float* __restrict__ x)
{
    const int idx = blockIdx.x * 256 + threadIdx.x;
    const int m  = idx >> 8;
    const int c4 = (idx & 255) * 4;
    float4 v = *(const float4*)(x + (size_t)m * D_ + c4);
    float vv[4] = {v.x, v.y, v.z, v.w};
    __nv_bfloat16 hi[4], lo[4];
    #pragma unroll
    for (int i = 0; i < 4; i++) {
        hi[i] = __float2bfloat16(vv[i]);
        lo[i] = __float2bfloat16(vv[i] - __bfloat162float(hi[i]));
    }
    __nv_bfloat16* dst = g_Ax + (size_t)m * KX + c4;
    *(uint2*)(dst)        = *(uint2*)hi;
    *(uint2*)(dst + 1024) = *(uint2*)hi;
    *(uint2*)(dst + 2048) = *(uint2*)lo;
}

// ------- conversion: all four W[K,N] -> Bt[N,3K] split [hi|lo|hi], z-grid ----
__global__ __launch_bounds__(1024) void convert_w_kernel(const float* __restrict__ Wq,
                                                         const float* __restrict__ Wk,
                                                         const float* __restrict__ Wv,
                                                         const float* __restrict__ Wo)
{
    __shared__ float t[32][33];
    const int z  = blockIdx.z;
    const float* W = (z == 0) ? Wq : ((z == 1) ? Wk : ((z == 2) ? Wv : Wo));
    __nv_bfloat16* Bt;
    if (z < 3) { Bt = g_Bqkv + (size_t)z * 1024 * KX; }
    else       { Bt = g_Bo; }

    const int tx = threadIdx.x & 31, ty = threadIdx.x >> 5;
    const int n0 = blockIdx.x * 32, k0 = blockIdx.y * 32;
    t[ty][tx] = W[(size_t)(k0 + ty) * D_ + n0 + tx];
    __syncthreads();
    const float v = t[tx][ty];   // = W[k0+tx][n0+ty]
    const __nv_bfloat16 hi = __float2bfloat16(v);
    const __nv_bfloat16 lo = __float2bfloat16(v - __bfloat162float(hi));
    __nv_bfloat16* dst = Bt + (size_t)(n0 + ty) * KX + k0 + tx;
    dst[0]    = hi;
    dst[1024] = lo;
    dst[2048] = hi;
}

// ------- conversion: Wb|Wfd|Wsd [1024,16] -> g_Bqkv rows 3072..3119 ----------
__global__ __launch_bounds__(256) void convert_small_w_kernel(const float* __restrict__ Wb,
                                                              const float* __restrict__ Wfd,
                                                              const float* __restrict__ Wsd)
{
    const int gid = blockIdx.x * 256 + threadIdx.x;   // 48*1024 = 49152
    const int o = gid >> 10;      // 0..47
    const int k = gid & 1023;
    const float* W = (o < 16) ? Wb : ((o < 32) ? Wfd : Wsd);
    const float v = W[(size_t)k * 16 + (o & 15)];
    const __nv_bfloat16 hi = __float2bfloat16(v);
    const __nv_bfloat16 lo = __float2bfloat16(v - __bfloat162float(hi));
    __nv_bfloat16* dst = g_Bqkv + (size_t)(3072 + o) * KX + k;
    dst[0]    = hi;
    dst[1024] = lo;
    dst[2048] = hi;
}

// ---------------- K2': decay/beta from GEMM columns 3072..3119 --------------
__global__ __launch_bounds__(256) void decay_kernel(const float* __restrict__ bfd,
                                                    const float* __restrict__ bsd)
{
    const int gid = blockIdx.x * 256 + threadIdx.x;   // 8192*48
    const int m = gid / 48;
    const int o = gid % 48;
    const float acc = g_qkv[(size_t)m * NX + 3072 + o];
    const int b = m >> 12;
    const int l = m & (L_-1);
    const int which = o >> 4, h = o & 15;
    const size_t idx = ((size_t)b*H_ + h)*L_ + l;
    if (which == 0)      g_beta[idx] = sigmoidf_(acc);
    else if (which == 1) g_logf[idx] = logf(sigmoidf_(acc + bfd[h]) + 1e-6f);
    else                 g_logs[idx] = logf(sigmoidf_(acc + bsd[h]) + 1e-6f);
}

// ---------------- K3: per-token prep ----------------
__global__ __launch_bounds__(128) void prep_kernel(const float* __restrict__ Wtf1,
                                                   const float* __restrict__ btf1,
                                                   const float* __restrict__ Wtf2,
                                                   const float* __restrict__ btf2)
{
    const int wip  = threadIdx.x >> 5;
    const int lane = threadIdx.x & 31;
    const size_t w = (size_t)blockIdx.x*4 + wip;
    const int bh = (int)(w / L_);
    const int l  = (int)(w % L_);
    const int b  = bh >> 4;
    const int h  = bh & 15;

    __shared__ float kbs[4][DK_];

    const size_t src = ((size_t)b*L_ + l)*NX + (size_t)h*DK_;
    float q0 = g_qkv[src + lane],          q1 = g_qkv[src + 32 + lane];
    float k0 = g_qkv[src + 1024 + lane],   k1 = g_qkv[src + 1024 + 32 + lane];
    float v0 = g_qkv[src + 2048 + lane],   v1 = g_qkv[src + 2048 + 32 + lane];

    float sq = q0*q0 + q1*q1;
    #pragma unroll
    for (int off = 16; off; off >>= 1) sq += __shfl_xor_sync(0xffffffffu, sq, off);
    float qinv = 1.0f / fmaxf(sqrtf(sq), 1e-12f);

    float sk = k0*k0 + k1*k1;
    #pragma unroll
    for (int off = 16; off; off >>= 1) sk += __shfl_xor_sync(0xffffffffu, sk, off);
    float kinv = 1.0f / fmaxf(sqrtf(sk), 1e-12f);

    const float beta = g_beta[(size_t)bh*L_ + l];
    const float kb0 = k0*kinv*beta, kb1 = k1*kinv*beta;

    const size_t dst = ((size_t)bh*L_ + l)*DK_;
    g_qn[dst + lane]      = q0*qinv;
    g_qn[dst + 32 + lane] = q1*qinv;
    g_kb[dst + lane]      = kb0;
    g_kb[dst + 32 + lane] = kb1;
    g_vs[dst + lane]      = v0*beta;
    g_vs[dst + 32 + lane] = v1*beta;

    kbs[wip][lane]      = kb0;
    kbs[wip][lane + 32] = kb1;
    __syncwarp();

    float hsum = btf1[lane];
    #pragma unroll 8
    for (int d = 0; d < DK_; d++) hsum = fmaf(kbs[wip][d], Wtf1[d*32 + lane], hsum);
    float sil = hsum / (1.0f + expf(-hsum));
    float acc = sil * Wtf2[lane];
    #pragma unroll
    for (int off = 16; off; off >>= 1) acc += __shfl_xor_sync(0xffffffffu, acc, off);

    if (lane == 0) {
        float tf = sigmoidf_(acc + btf2[0]);
        tf = fminf(fmaxf(tf, 0.01f), 0.99f);
        g_alpha[(size_t)bh*L_ + l] = 0.5f + 0.3f*tf;
    }
}

// ---------------- K4: per-(b,h) cumsum scan (double) ----------------
__global__ __launch_bounds__(256) void scan_kernel()
{
    const int bh  = blockIdx.x;
    const int tid = threadIdx.x;
    const int PER = L_ / 256;
    __shared__ double s[256];

    for (int fs = 0; fs < 2; fs++) {
        const float* lg = (fs == 0) ? g_logf : g_logs;
        float*       wv = (fs == 0) ? g_fw   : g_sw;

        double loc[16];
        double run = 0.0;
        const size_t base = (size_t)bh*L_ + (size_t)tid*PER;
        #pragma unroll
        for (int i = 0; i < PER; i++) { run += (double)lg[base + i]; loc[i] = run; }
        s[tid] = run;
        __syncthreads();
        for (int off = 1; off < 256; off <<= 1) {
            double v = (tid >= off) ? s[tid - off] : 0.0;
            __syncthreads();
            s[tid] += v;
            __syncthreads();
        }
        const double excl  = s[tid] - run;
        const double total = s[255];
        __syncthreads();

        double acc = 0.0;
        #pragma unroll
        for (int i = 0; i < PER; i++) {
            double ww = exp(total - (excl + loc[i]));
            wv[base + i] = (float)ww;
            acc += ww;
        }
        s[tid] = acc;
        __syncthreads();
        for (int off = 128; off > 0; off >>= 1) {
            if (tid < off) s[tid] += s[tid + off];
            __syncthreads();
        }
        if (tid == 0) g_wsum[bh*2 + fs] = (float)s[0];
        __syncthreads();
    }
}

// ---------------- K5: partial KV outer-product states (256 tok/chunk) -------
__global__ __launch_bounds__(256) void outer_kernel()
{
    const int bh  = blockIdx.y;
    const int ch  = blockIdx.x;
    const int tid = threadIdx.x;
    __shared__ float ks [64*64];
    __shared__ float vsh[64*64];
    __shared__ float fsh[64], ssh[64];

    const int d0 = (tid >> 4) * 4;
    const int e0 = (tid & 15) * 4;
    float af[4][4], as_[4][4];
    #pragma unroll
    for (int i = 0; i < 4; i++)
        #pragma unroll
        for (int j = 0; j < 4; j++) { af[i][j] = 0.f; as_[i][j] = 0.f; }

    for (int sub = 0; sub < CHT/64; sub++) {
        const int l0 = ch * CHT + sub * 64;
        const float* kbp = g_kb + ((size_t)bh*L_ + l0)*DK_;
        const float* vsp = g_vs + ((size_t)bh*L_ + l0)*DK_;
        for (int i = tid*4; i < 4096; i += 1024) {
            *(float4*)(ks + i)  = *(const float4*)(kbp + i);
            *(float4*)(vsh + i) = *(const float4*)(vsp + i);
        }
        if (tid < 64) {
            fsh[tid] = g_fw[(size_t)bh*L_ + l0 + tid];
            ssh[tid] = g_sw[(size_t)bh*L_ + l0 + tid];
        }
        __syncthreads();

        for (int ll = 0; ll < 64; ll++) {
            const float f = fsh[ll], sdec = ssh[ll];
            float kd[4], ve[4];
            #pragma unroll
            for (int i = 0; i < 4; i++) kd[i] = ks[ll*64 + d0 + i];
            #pragma unroll
            for (int j = 0; j < 4; j++) ve[j] = vsh[ll*64 + e0 + j];
            #pragma unroll
            for (int i = 0; i < 4; i++) {
                const float kf = kd[i]*f, ksl = kd[i]*sdec;
                #pragma unroll
                for (int j = 0; j < 4; j++) {
                    af[i][j]  = fmaf(kf,  ve[j], af[i][j]);
                    as_[i][j] = fmaf(ksl, ve[j], as_[i][j]);
                }
            }
        }
        __syncthreads();
    }

    float* pf = g_part + ((size_t)(bh*NCHUNK + ch))*8192;
    #pragma unroll
    for (int i = 0; i < 4; i++)
        #pragma unroll
        for (int j = 0; j < 4; j++) {
            pf[(d0+i)*64 + e0 + j]        = af[i][j];
            pf[4096 + (d0+i)*64 + e0 + j] = as_[i][j];
        }
}

// ---------------- K6: reduce partials + normalize (grid 32x8) ----------------
__global__ __launch_bounds__(256) void reduce_kernel()
{
    const int bh  = blockIdx.x;
    const int seg = blockIdx.y;
    const int idx = seg * 1024 + threadIdx.x * 4;
    const int fs  = idx >> 12;
    float4 sum = make_float4(0.f, 0.f, 0.f, 0.f);
    for (int c = 0; c < NCHUNK; c++) {
        float4 v = *(const float4*)(g_part + ((size_t)(bh*NCHUNK + c))*8192 + idx);
        sum.x += v.x; sum.y += v.y; sum.z += v.z; sum.w += v.w;
    }
    const float inv = 1.0f / (g_wsum[bh*2 + fs] + 1e-6f);
    sum.x *= inv; sum.y *= inv; sum.z *= inv; sum.w *= inv;
    *(float4*)(g_M + (size_t)bh*8192 + idx) = sum;
}

// ---------------- K7: output mix -> writes bf16 split A for final GEMM ------
__global__ __launch_bounds__(256) void outproj_kernel()
{
    const int bh  = blockIdx.y;
    const int lt  = blockIdx.x;
    const int tid = threadIdx.x;
    __shared__ float qs[32*64];
    __shared__ float Mf[64*64];
    __shared__ float Ms[64*64];
    __shared__ float al[32];

    const int l0 = lt * 32;
    const float* qp = g_qn + ((size_t)bh*L_ + l0)*DK_;
    for (int i = tid*4; i < 2048; i += 1024) *(float4*)(qs + i) = *(const float4*)(qp + i);
    const float* Mp = g_M + (size_t)bh*8192;
    for (int i = tid*4; i < 4096; i += 1024) {
        *(float4*)(Mf + i) = *(const float4*)(Mp + i);
        *(float4*)(Ms + i) = *(const float4*)(Mp + 4096 + i);
    }
    if (tid < 32) al[tid] = g_alpha[(size_t)bh*L_ + l0 + tid];
    __syncthreads();

    const int li = tid >> 3;
    const int e0 = (tid & 7) * 8;
    float of[8], os[8];
    #pragma unroll
    for (int j = 0; j < 8; j++) { of[j] = 0.f; os[j] = 0.f; }

    #pragma unroll 4
    for (int d = 0; d < 64; d++) {
        const float qv = qs[li*64 + d];
        #pragma unroll
        for (int j = 0; j < 8; j++) {
            of[j] = fmaf(qv, Mf[d*64 + e0 + j], of[j]);
            os[j] = fmaf(qv, Ms[d*64 + e0 + j], os[j]);
        }
    }
    const float a = al[li];
    const int b = bh >> 4, h = bh & 15;
    const size_t m = (size_t)b*L_ + l0 + li;
    __nv_bfloat16 hi[8], lo[8];
    #pragma unroll
    for (int j = 0; j < 8; j++) {
        const float val = a*of[j] + (1.0f - a)*os[j];
        hi[j] = __float2bfloat16(val);
        lo[j] = __float2bfloat16(val - __bfloat162float(hi[j]));
    }
    __nv_bfloat16* dst = g_Ao + m*KX + (size_t)h*DK_ + e0;
    *(uint4*)(dst)        = *(uint4*)hi;
    *(uint4*)(dst + 1024) = *(uint4*)hi;
    *(uint4*)(dst + 2048) = *(uint4*)lo;
}

// ---------------- launch ----------------
extern "C" void kernel_launch(void* const* d_in, const int* in_sizes, int n_in,
                              void* d_out, int out_size)
{
    const float* x    = (const float*)d_in[0];
    const float* Wq   = (const float*)d_in[1];
    const float* Wk   = (const float*)d_in[2];
    const float* Wv   = (const float*)d_in[3];
    const float* Wb   = (const float*)d_in[4];
    const float* Wo   = (const float*)d_in[5];
    const float* Wfd  = (const float*)d_in[6];
    const float* bfd  = (const float*)d_in[7];
    const float* Wsd  = (const float*)d_in[8];
    const float* bsd  = (const float*)d_in[9];
    const float* Wtf1 = (const float*)d_in[10];
    const float* btf1 = (const float*)d_in[11];
    const float* Wtf2 = (const float*)d_in[12];
    const float* btf2 = (const float*)d_in[13];
    float* out = (float*)d_out;

    __nv_bfloat16 *Ax, *Ao, *Bqkv, *Bo;
    float *qkv;
    cudaGetSymbolAddress((void**)&Ax,   g_Ax);
    cudaGetSymbolAddress((void**)&Ao,   g_Ao);
    cudaGetSymbolAddress((void**)&Bqkv, g_Bqkv);
    cudaGetSymbolAddress((void**)&Bo,   g_Bo);
    cudaGetSymbolAddress((void**)&qkv,  g_qkv);

    cudaFuncSetAttribute(gemm_bf16_mma, cudaFuncAttributeMaxDynamicSharedMemorySize, GSMEM);

    // conversions
    convert_x_kernel<<<(MROWS * D_ / 4) / 256, 256>>>(x);
    dim3 wgrid(D_/32, D_/32, 4);
    convert_w_kernel<<<wgrid, 1024>>>(Wq, Wk, Wv, Wo);
    convert_small_w_kernel<<<(48*1024)/256, 256>>>(Wb, Wfd, Wsd);

    // fused q|k|v|decay GEMM: [8192, 3200] = Ax[8192,3072k] * Bqkv[3200n,3072k]^T
    dim3 qkvgrid(NX/128, MROWS/128);     // (25, 64)
    gemm_bf16_mma<<<qkvgrid, 256, GSMEM>>>(Ax, Bqkv, qkv, MROWS, NX, KX);

    decay_kernel<<<(MROWS*48)/256, 256>>>(bfd, bsd);
    prep_kernel<<<(BH * L_) / 4, 128>>>(Wtf1, btf1, Wtf2, btf2);
    scan_kernel<<<BH, 256>>>();

    dim3 ogrid(NCHUNK, BH);                  // (16, 32)
    outer_kernel<<<ogrid, 256>>>();
    dim3 rgrid(BH, 8);
    reduce_kernel<<<rgrid, 256>>>();

    dim3 pgrid(L_ / 32, BH);
    outproj_kernel<<<pgrid, 256>>>();

    // final GEMM: out[8192,1024] = Ao[8192,3072k] * Bo[1024n,3072k]^T
    dim3 fgrid(D_/128, MROWS/128);       // (8, 64)
    gemm_bf16_mma<<<fgrid, 256, GSMEM>>>(Ao, Bo, out, MROWS, D_, KX);
}

// round 13
// speedup vs baseline: 1.3330x; 1.0146x over previous
#include <cuda_runtime.h>
#include <cuda_bf16.h>
#include <math.h>
#include <stdint.h>

// Problem constants
#define B_ 2
#define L_ 4096
#define D_ 1024
#define H_ 16
#define DK_ 64
#define MROWS (B_*L_)          // 8192
#define BH (B_*H_)             // 32
#define NCHUNK 16              // 256 tokens per partial chunk
#define CHT 256                // tokens per chunk
#define KX 3072                // expanded K (3x bf16 split)
#define NX 3200                // QKV GEMM N: 3072 qkv + 48 decay proj + 80 pad

// ---------------- scratch (device globals; allocation-free) ----------------
__device__ __align__(16) __nv_bfloat16 g_Ax  [MROWS*KX];   // x split  [M, 3072]  (hi|hi|lo)
__device__ __align__(16) __nv_bfloat16 g_Ao  [MROWS*KX];   // o split  [M, 3072]
__device__ __align__(16) __nv_bfloat16 g_Bqkv[NX*KX];      // Wq|Wk|Wv|Wb|Wfd|Wsd|0-pad [3200 N, 3072 K]
__device__ __align__(16) __nv_bfloat16 g_Bo  [D_*KX];      // Wo [1024 N, 3072 K]
__device__ float g_qkv[MROWS*NX];    // q|k|v|decay linear outputs [M, 3200]
__device__ float g_qn [MROWS*D_];    // [bh][l][dk]
__device__ float g_kb [MROWS*D_];
__device__ float g_vs [MROWS*D_];
__device__ float g_beta [BH*L_];
__device__ float g_logf [BH*L_];
__device__ float g_logs [BH*L_];
__device__ float g_fw   [BH*L_];
__device__ float g_sw   [BH*L_];
__device__ float g_alpha[BH*L_];
__device__ float g_wsum [BH*2];
__device__ float g_part [BH*NCHUNK*2*DK_*DK_];   // 4.2M floats
__device__ float g_M    [BH*2*DK_*DK_];

__device__ __forceinline__ float sigmoidf_(float x){ return 1.0f/(1.0f+expf(-x)); }

// ======================= PTX helpers (sm_80-compatible) =====================
__device__ __forceinline__ uint32_t smem_u32(const void* p){
    return (uint32_t)__cvta_generic_to_shared(p);
}
__device__ __forceinline__ void cp_async16(uint32_t saddr, const void* gaddr){
    asm volatile("cp.async.cg.shared.global [%0], [%1], 16;" :: "r"(saddr), "l"(gaddr));
}
__device__ __forceinline__ void cp_commit(){ asm volatile("cp.async.commit_group;"); }
#define CP_WAIT(n) asm volatile("cp.async.wait_group %0;" :: "n"(n))

__device__ __forceinline__ void ldmat_x4(uint32_t* r, uint32_t addr){
    asm volatile("ldmatrix.sync.aligned.m8n8.x4.shared.b16 {%0,%1,%2,%3}, [%4];"
        : "=r"(r[0]), "=r"(r[1]), "=r"(r[2]), "=r"(r[3]) : "r"(addr));
}
__device__ __forceinline__ void mma16816(float* c, const uint32_t* a, uint32_t b0, uint32_t b1){
    asm volatile("mma.sync.aligned.m16n8k16.row.col.f32.bf16.bf16.f32 "
        "{%0,%1,%2,%3}, {%4,%5,%6,%7}, {%8,%9}, {%0,%1,%2,%3};"
        : "+f"(c[0]), "+f"(c[1]), "+f"(c[2]), "+f"(c[3])
        : "r"(a[0]), "r"(a[1]), "r"(a[2]), "r"(a[3]), "r"(b0), "r"(b1));
}

// ====== HMMA bf16 GEMM: C[M,N] = A[M,K] * B[N,K]^T (both row-major, bf16) ===
// Block tile 128x128, K-chunk 64, 3-stage cp.async pipeline, 2 CTAs/SM.
// 8 warps as 4M x 2N, warp tile 32x64. Half the barrier count of BKC=32.
#define BKC 64
#define SSTR 72                        // smem row stride in bf16 (144B = 9x16B, conflict-free)
#define HTILE (128*SSTR*2)             // 18432 B (one operand per stage)
#define STG (2*HTILE)                  // 36864 B per stage (A+B)
#define NST 3
#define GSMEM (NST*STG)                // 110592 B

__global__ __launch_bounds__(256, 2)
void gemm_bf16_mma(const __nv_bfloat16* __restrict__ A,
                   const __nv_bfloat16* __restrict__ B,
                   float* __restrict__ C, int M, int N, int K)
{
    extern __shared__ char sm[];
    const uint32_t sbase = smem_u32(sm);
    const int tid  = threadIdx.x;
    const int wid  = tid >> 5;
    const int lane = tid & 31;
    const int wm   = wid & 3;
    const int wn   = wid >> 2;

    const int m0 = blockIdx.y * 128;
    const int n0 = blockIdx.x * 128;
    const __nv_bfloat16* Ag = A + (size_t)m0 * K;
    const __nv_bfloat16* Bg = B + (size_t)n0 * K;

    // global->smem mapping: 4 x 16B segments per thread per operand
    const int lrow = tid >> 3;            // 0..31
    const int cs   = (tid & 7) * 8;       // bf16 col {0,8,...,56}
    uint32_t oA[4], oB[4];
    #pragma unroll
    for (int t = 0; t < 4; t++) {
        oA[t] = (uint32_t)((lrow + t*32) * SSTR + cs) * 2;
        oB[t] = HTILE + oA[t];
    }

    // ldmatrix lane offsets (byte offsets within a stage)
    const int arow = (lane & 15);
    const int akof = (lane >> 4) * 8;
    uint32_t aoff[2];
    #pragma unroll
    for (int mi = 0; mi < 2; mi++)
        aoff[mi] = (uint32_t)((wm*32 + mi*16 + arow) * SSTR + akof) * 2;

    const int brow = (lane & 7) + ((lane >> 4) << 3);
    const int bkof = ((lane >> 3) & 1) * 8;
    uint32_t boff[4];
    #pragma unroll
    for (int ni = 0; ni < 4; ni++)
        boff[ni] = HTILE + (uint32_t)((wn*64 + ni*16 + brow) * SSTR + bkof) * 2;

    float acc[2][8][4];
    #pragma unroll
    for (int mi = 0; mi < 2; mi++)
        #pragma unroll
        for (int j = 0; j < 8; j++)
            #pragma unroll
            for (int t = 0; t < 4; t++) acc[mi][j][t] = 0.0f;

    const int nch = K / BKC;

    // prologue: load chunks 0..NST-2 into stages 0..NST-2
    #pragma unroll
    for (int s = 0; s < NST - 1; s++) {
        const size_t kc = (size_t)s * BKC;
        const uint32_t sa = sbase + s * STG;
        #pragma unroll
        for (int t = 0; t < 4; t++) {
            cp_async16(sa + oA[t], Ag + (size_t)(lrow + t*32) * K + kc + cs);
            cp_async16(sa + oB[t], Bg + (size_t)(lrow + t*32) * K + kc + cs);
        }
        cp_commit();
    }

    for (int c = 0; c < nch; c++) {
        CP_WAIT(NST - 2);
        __syncthreads();

        // prefetch chunk c+NST-1 into stage (c+NST-1)%NST (== stage of iter c-1)
        {
            const int cn = c + NST - 1;
            if (cn < nch) {
                const size_t kc = (size_t)cn * BKC;
                uint32_t sa = sbase;
                { const int s = cn % NST; sa += (uint32_t)s * STG; }
                #pragma unroll
                for (int t = 0; t < 4; t++) {
                    cp_async16(sa + oA[t], Ag + (size_t)(lrow + t*32) * K + kc + cs);
                    cp_async16(sa + oB[t], Bg + (size_t)(lrow + t*32) * K + kc + cs);
                }
            }
            cp_commit();
        }

        uint32_t so = sbase;
        { const int s = c % NST; so += (uint32_t)s * STG; }

        #pragma unroll
        for (int kk = 0; kk < 4; kk++) {
            const uint32_t ko = (uint32_t)(kk * 16) * 2;
            uint32_t a[2][4];
            #pragma unroll
            for (int mi = 0; mi < 2; mi++) ldmat_x4(a[mi], so + aoff[mi] + ko);
            uint32_t bf[4][4];
            #pragma unroll
            for (int ni = 0; ni < 4; ni++) ldmat_x4(bf[ni], so + boff[ni] + ko);
            #pragma unroll
            for (int mi = 0; mi < 2; mi++)
                #pragma unroll
                for (int ni = 0; ni < 4; ni++) {
                    mma16816(acc[mi][ni*2+0], a[mi], bf[ni][0], bf[ni][1]);
                    mma16816(acc[mi][ni*2+1], a[mi], bf[ni][2], bf[ni][3]);
                }
        }
    }

    // epilogue: direct fp32 stores
    const int rr = lane >> 2;
    const int cc = (lane & 3) * 2;
    #pragma unroll
    for (int mi = 0; mi < 2; mi++) {
        const int rowb = m0 + wm*32 + mi*16;
        #pragma unroll
        for (int j = 0; j < 8; j++) {
            const int col = n0 + wn*64 + j*8 + cc;
            float2 v0 = make_float2(acc[mi][j][0], acc[mi][j][1]);
            float2 v1 = make_float2(acc[mi][j][2], acc[mi][j][3]);
            *(float2*)(C + (size_t)(rowb + rr)     * N + col) = v0;
            *(float2*)(C + (size_t)(rowb + rr + 8) * N + col) = v1;
        }
    }
}

// ---------------- conversion: x -> bf16 split [hi|hi|lo] ----------------
__global__ __launch_bounds__(256) void convert_x_kernel(const float* __restrict__ x)
{
    const int idx = blockIdx.x * 256 + threadIdx.x;
    const int m  = idx >> 8;
    const int c4 = (idx & 255) * 4;
    float4 v = *(const float4*)(x + (size_t)m * D_ + c4);
    float vv[4] = {v.x, v.y, v.z, v.w};
    __nv_bfloat16 hi[4], lo[4];
    #pragma unroll
    for (int i = 0; i < 4; i++) {
        hi[i] = __float2bfloat16(vv[i]);
        lo[i] = __float2bfloat16(vv[i] - __bfloat162float(hi[i]));
    }
    __nv_bfloat16* dst = g_Ax + (size_t)m * KX + c4;
    *(uint2*)(dst)        = *(uint2*)hi;
    *(uint2*)(dst + 1024) = *(uint2*)hi;
    *(uint2*)(dst + 2048) = *(uint2*)lo;
}

// ------- conversion: all four W[K,N] -> Bt[N,3K] split [hi|lo|hi], z-grid ----
__global__ __launch_bounds__(1024) void convert_w_kernel(const float* __restrict__ Wq,
                                                         const float* __restrict__ Wk,
                                                         const float* __restrict__ Wv,
                                                         const float* __restrict__ Wo)
{
    __shared__ float t[32][33];
    const int z  = blockIdx.z;
    const float* W = (z == 0) ? Wq : ((z == 1) ? Wk : ((z == 2) ? Wv : Wo));
    __nv_bfloat16* Bt;
    if (z < 3) { Bt = g_Bqkv + (size_t)z * 1024 * KX; }
    else       { Bt = g_Bo; }

    const int tx = threadIdx.x & 31, ty = threadIdx.x >> 5;
    const int n0 = blockIdx.x * 32, k0 = blockIdx.y * 32;
    t[ty][tx] = W[(size_t)(k0 + ty) * D_ + n0 + tx];
    __syncthreads();
    const float v = t[tx][ty];   // = W[k0+tx][n0+ty]
    const __nv_bfloat16 hi = __float2bfloat16(v);
    const __nv_bfloat16 lo = __float2bfloat16(v - __bfloat162float(hi));
    __nv_bfloat16* dst = Bt + (size_t)(n0 + ty) * KX + k0 + tx;
    dst[0]    = hi;
    dst[1024] = lo;
    dst[2048] = hi;
}

// ------- conversion: Wb|Wfd|Wsd [1024,16] -> g_Bqkv rows 3072..3119 ----------
__global__ __launch_bounds__(256) void convert_small_w_kernel(const float* __restrict__ Wb,
                                                              const float* __restrict__ Wfd,
                                                              const float* __restrict__ Wsd)
{
    const int gid = blockIdx.x * 256 + threadIdx.x;   // 48*1024 = 49152
    const int o = gid >> 10;      // 0..47
    const int k = gid & 1023;
    const float* W = (o < 16) ? Wb : ((o < 32) ? Wfd : Wsd);
    const float v = W[(size_t)k * 16 + (o & 15)];
    const __nv_bfloat16 hi = __float2bfloat16(v);
    const __nv_bfloat16 lo = __float2bfloat16(v - __bfloat162float(hi));
    __nv_bfloat16* dst = g_Bqkv + (size_t)(3072 + o) * KX + k;
    dst[0]    = hi;
    dst[1024] = lo;
    dst[2048] = hi;
}

// ---------------- K2': decay/beta from GEMM columns 3072..3119 --------------
__global__ __launch_bounds__(256) void decay_kernel(const float* __restrict__ bfd,
                                                    const float* __restrict__ bsd)
{
    const int gid = blockIdx.x * 256 + threadIdx.x;   // 8192*48
    const int m = gid / 48;
    const int o = gid % 48;
    const float acc = g_qkv[(size_t)m * NX + 3072 + o];
    const int b = m >> 12;
    const int l = m & (L_-1);
    const int which = o >> 4, h = o & 15;
    const size_t idx = ((size_t)b*H_ + h)*L_ + l;
    if (which == 0)      g_beta[idx] = sigmoidf_(acc);
    else if (which == 1) g_logf[idx] = logf(sigmoidf_(acc + bfd[h]) + 1e-6f);
    else                 g_logs[idx] = logf(sigmoidf_(acc + bsd[h]) + 1e-6f);
}

// ---------------- K3: per-token prep ----------------
__global__ __launch_bounds__(128) void prep_kernel(const float* __restrict__ Wtf1,
                                                   const float* __restrict__ btf1,
                                                   const float* __restrict__ Wtf2,
                                                   const float* __restrict__ btf2)
{
    const int wip  = threadIdx.x >> 5;
    const int lane = threadIdx.x & 31;
    const size_t w = (size_t)blockIdx.x*4 + wip;
    const int bh = (int)(w / L_);
    const int l  = (int)(w % L_);
    const int b  = bh >> 4;
    const int h  = bh & 15;

    __shared__ float kbs[4][DK_];

    const size_t src = ((size_t)b*L_ + l)*NX + (size_t)h*DK_;
    float q0 = g_qkv[src + lane],          q1 = g_qkv[src + 32 + lane];
    float k0 = g_qkv[src + 1024 + lane],   k1 = g_qkv[src + 1024 + 32 + lane];
    float v0 = g_qkv[src + 2048 + lane],   v1 = g_qkv[src + 2048 + 32 + lane];

    float sq = q0*q0 + q1*q1;
    #pragma unroll
    for (int off = 16; off; off >>= 1) sq += __shfl_xor_sync(0xffffffffu, sq, off);
    float qinv = 1.0f / fmaxf(sqrtf(sq), 1e-12f);

    float sk = k0*k0 + k1*k1;
    #pragma unroll
    for (int off = 16; off; off >>= 1) sk += __shfl_xor_sync(0xffffffffu, sk, off);
    float kinv = 1.0f / fmaxf(sqrtf(sk), 1e-12f);

    const float beta = g_beta[(size_t)bh*L_ + l];
    const float kb0 = k0*kinv*beta, kb1 = k1*kinv*beta;

    const size_t dst = ((size_t)bh*L_ + l)*DK_;
    g_qn[dst + lane]      = q0*qinv;
    g_qn[dst + 32 + lane] = q1*qinv;
    g_kb[dst + lane]      = kb0;
    g_kb[dst + 32 + lane] = kb1;
    g_vs[dst + lane]      = v0*beta;
    g_vs[dst + 32 + lane] = v1*beta;

    kbs[wip][lane]      = kb0;
    kbs[wip][lane + 32] = kb1;
    __syncwarp();

    float hsum = btf1[lane];
    #pragma unroll 8
    for (int d = 0; d < DK_; d++) hsum = fmaf(kbs[wip][d], Wtf1[d*32 + lane], hsum);
    float sil = hsum / (1.0f + expf(-hsum));
    float acc = sil * Wtf2[lane];
    #pragma unroll
    for (int off = 16; off; off >>= 1) acc += __shfl_xor_sync(0xffffffffu, acc, off);

    if (lane == 0) {
        float tf = sigmoidf_(acc + btf2[0]);
        tf = fminf(fmaxf(tf, 0.01f), 0.99f);
        g_alpha[(size_t)bh*L_ + l] = 0.5f + 0.3f*tf;
    }
}

// ---------------- K4: per-(b,h) cumsum scan (double) ----------------
__global__ __launch_bounds__(256) void scan_kernel()
{
    const int bh  = blockIdx.x;
    const int tid = threadIdx.x;
    const int PER = L_ / 256;
    __shared__ double s[256];

    for (int fs = 0; fs < 2; fs++) {
        const float* lg = (fs == 0) ? g_logf : g_logs;
        float*       wv = (fs == 0) ? g_fw   : g_sw;

        double loc[16];
        double run = 0.0;
        const size_t base = (size_t)bh*L_ + (size_t)tid*PER;
        #pragma unroll
        for (int i = 0; i < PER; i++) { run += (double)lg[base + i]; loc[i] = run; }
        s[tid] = run;
        __syncthreads();
        for (int off = 1; off < 256; off <<= 1) {
            double v = (tid >= off) ? s[tid - off] : 0.0;
            __syncthreads();
            s[tid] += v;
            __syncthreads();
        }
        const double excl  = s[tid] - run;
        const double total = s[255];
        __syncthreads();

        double acc = 0.0;
        #pragma unroll
        for (int i = 0; i < PER; i++) {
            double ww = exp(total - (excl + loc[i]));
            wv[base + i] = (float)ww;
            acc += ww;
        }
        s[tid] = acc;
        __syncthreads();
        for (int off = 128; off > 0; off >>= 1) {
            if (tid < off) s[tid] += s[tid + off];
            __syncthreads();
        }
        if (tid == 0) g_wsum[bh*2 + fs] = (float)s[0];
        __syncthreads();
    }
}

// ---------------- K5: partial KV outer-product states (256 tok/chunk) -------
__global__ __launch_bounds__(256) void outer_kernel()
{
    const int bh  = blockIdx.y;
    const int ch  = blockIdx.x;
    const int tid = threadIdx.x;
    __shared__ float ks [64*64];
    __shared__ float vsh[64*64];
    __shared__ float fsh[64], ssh[64];

    const int d0 = (tid >> 4) * 4;
    const int e0 = (tid & 15) * 4;
    float af[4][4], as_[4][4];
    #pragma unroll
    for (int i = 0; i < 4; i++)
        #pragma unroll
        for (int j = 0; j < 4; j++) { af[i][j] = 0.f; as_[i][j] = 0.f; }

    for (int sub = 0; sub < CHT/64; sub++) {
        const int l0 = ch * CHT + sub * 64;
        const float* kbp = g_kb + ((size_t)bh*L_ + l0)*DK_;
        const float* vsp = g_vs + ((size_t)bh*L_ + l0)*DK_;
        for (int i = tid*4; i < 4096; i += 1024) {
            *(float4*)(ks + i)  = *(const float4*)(kbp + i);
            *(float4*)(vsh + i) = *(const float4*)(vsp + i);
        }
        if (tid < 64) {
            fsh[tid] = g_fw[(size_t)bh*L_ + l0 + tid];
            ssh[tid] = g_sw[(size_t)bh*L_ + l0 + tid];
        }
        __syncthreads();

        for (int ll = 0; ll < 64; ll++) {
            const float f = fsh[ll], sdec = ssh[ll];
            float kd[4], ve[4];
            #pragma unroll
            for (int i = 0; i < 4; i++) kd[i] = ks[ll*64 + d0 + i];
            #pragma unroll
            for (int j = 0; j < 4; j++) ve[j] = vsh[ll*64 + e0 + j];
            #pragma unroll
            for (int i = 0; i < 4; i++) {
                const float kf = kd[i]*f, ksl = kd[i]*sdec;
                #pragma unroll
                for (int j = 0; j < 4; j++) {
                    af[i][j]  = fmaf(kf,  ve[j], af[i][j]);
                    as_[i][j] = fmaf(ksl, ve[j], as_[i][j]);
                }
            }
        }
        __syncthreads();
    }

    float* pf = g_part + ((size_t)(bh*NCHUNK + ch))*8192;
    #pragma unroll
    for (int i = 0; i < 4; i++)
        #pragma unroll
        for (int j = 0; j < 4; j++) {
            pf[(d0+i)*64 + e0 + j]        = af[i][j];
            pf[4096 + (d0+i)*64 + e0 + j] = as_[i][j];
        }
}

// ---------------- K6: reduce partials + normalize (grid 32x8) ----------------
__global__ __launch_bounds__(256) void reduce_kernel()
{
    const int bh  = blockIdx.x;
    const int seg = blockIdx.y;
    const int idx = seg * 1024 + threadIdx.x * 4;
    const int fs  = idx >> 12;
    float4 sum = make_float4(0.f, 0.f, 0.f, 0.f);
    for (int c = 0; c < NCHUNK; c++) {
        float4 v = *(const float4*)(g_part + ((size_t)(bh*NCHUNK + c))*8192 + idx);
        sum.x += v.x; sum.y += v.y; sum.z += v.z; sum.w += v.w;
    }
    const float inv = 1.0f / (g_wsum[bh*2 + fs] + 1e-6f);
    sum.x *= inv; sum.y *= inv; sum.z *= inv; sum.w *= inv;
    *(float4*)(g_M + (size_t)bh*8192 + idx) = sum;
}

// ---------------- K7: output mix -> writes bf16 split A for final GEMM ------
__global__ __launch_bounds__(256) void outproj_kernel()
{
    const int bh  = blockIdx.y;
    const int lt  = blockIdx.x;
    const int tid = threadIdx.x;
    __shared__ float qs[32*64];
    __shared__ float Mf[64*64];
    __shared__ float Ms[64*64];
    __shared__ float al[32];

    const int l0 = lt * 32;
    const float* qp = g_qn + ((size_t)bh*L_ + l0)*DK_;
    for (int i = tid*4; i < 2048; i += 1024) *(float4*)(qs + i) = *(const float4*)(qp + i);
    const float* Mp = g_M + (size_t)bh*8192;
    for (int i = tid*4; i < 4096; i += 1024) {
        *(float4*)(Mf + i) = *(const float4*)(Mp + i);
        *(float4*)(Ms + i) = *(const float4*)(Mp + 4096 + i);
    }
    if (tid < 32) al[tid] = g_alpha[(size_t)bh*L_ + l0 + tid];
    __syncthreads();

    const int li = tid >> 3;
    const int e0 = (tid & 7) * 8;
    float of[8], os[8];
    #pragma unroll
    for (int j = 0; j < 8; j++) { of[j] = 0.f; os[j] = 0.f; }

    #pragma unroll 4
    for (int d = 0; d < 64; d++) {
        const float qv = qs[li*64 + d];
        #pragma unroll
        for (int j = 0; j < 8; j++) {
            of[j] = fmaf(qv, Mf[d*64 + e0 + j], of[j]);
            os[j] = fmaf(qv, Ms[d*64 + e0 + j], os[j]);
        }
    }
    const float a = al[li];
    const int b = bh >> 4, h = bh & 15;
    const size_t m = (size_t)b*L_ + l0 + li;
    __nv_bfloat16 hi[8], lo[8];
    #pragma unroll
    for (int j = 0; j < 8; j++) {
        const float val = a*of[j] + (1.0f - a)*os[j];
        hi[j] = __float2bfloat16(val);
        lo[j] = __float2bfloat16(val - __bfloat162float(hi[j]));
    }
    __nv_bfloat16* dst = g_Ao + m*KX + (size_t)h*DK_ + e0;
    *(uint4*)(dst)        = *(uint4*)hi;
    *(uint4*)(dst + 1024) = *(uint4*)hi;
    *(uint4*)(dst + 2048) = *(uint4*)lo;
}

// ---------------- launch ----------------
extern "C" void kernel_launch(void* const* d_in, const int* in_sizes, int n_in,
                              void* d_out, int out_size)
{
    const float* x    = (const float*)d_in[0];
    const float* Wq   = (const float*)d_in[1];
    const float* Wk   = (const float*)d_in[2];
    const float* Wv   = (const float*)d_in[3];
    const float* Wb   = (const float*)d_in[4];
    const float* Wo   = (const float*)d_in[5];
    const float* Wfd  = (const float*)d_in[6];
    const float* bfd  = (const float*)d_in[7];
    const float* Wsd  = (const float*)d_in[8];
    const float* bsd  = (const float*)d_in[9];
    const float* Wtf1 = (const float*)d_in[10];
    const float* btf1 = (const float*)d_in[11];
    const float* Wtf2 = (const float*)d_in[12];
    const float* btf2 = (const float*)d_in[13];
    float* out = (float*)d_out;

    __nv_bfloat16 *Ax, *Ao, *Bqkv, *Bo;
    float *qkv;
    cudaGetSymbolAddress((void**)&Ax,   g_Ax);
    cudaGetSymbolAddress((void**)&Ao,   g_Ao);
    cudaGetSymbolAddress((void**)&Bqkv, g_Bqkv);
    cudaGetSymbolAddress((void**)&Bo,   g_Bo);
    cudaGetSymbolAddress((void**)&qkv,  g_qkv);

    cudaFuncSetAttribute(gemm_bf16_mma, cudaFuncAttributeMaxDynamicSharedMemorySize, GSMEM);

    // conversions
    convert_x_kernel<<<(MROWS * D_ / 4) / 256, 256>>>(x);
    dim3 wgrid(D_/32, D_/32, 4);
    convert_w_kernel<<<wgrid, 1024>>>(Wq, Wk, Wv, Wo);
    convert_small_w_kernel<<<(48*1024)/256, 256>>>(Wb, Wfd, Wsd);

    // fused q|k|v|decay GEMM: [8192, 3200] = Ax[8192,3072k] * Bqkv[3200n,3072k]^T
    dim3 qkvgrid(NX/128, MROWS/128);     // (25, 64)
    gemm_bf16_mma<<<qkvgrid, 256, GSMEM>>>(Ax, Bqkv, qkv, MROWS, NX, KX);

    decay_kernel<<<(MROWS*48)/256, 256>>>(bfd, bsd);
    prep_kernel<<<(BH * L_) / 4, 128>>>(Wtf1, btf1, Wtf2, btf2);
    scan_kernel<<<BH, 256>>>();

    dim3 ogrid(NCHUNK, BH);                  // (16, 32)
    outer_kernel<<<ogrid, 256>>>();
    dim3 rgrid(BH, 8);
    reduce_kernel<<<rgrid, 256>>>();

    dim3 pgrid(L_ / 32, BH);
    outproj_kernel<<<pgrid, 256>>>();

    // final GEMM: out[8192,1024] = Ao[8192,3072k] * Bo[1024n,3072k]^T
    dim3 fgrid(D_/128, MROWS/128);       // (8, 64)
    gemm_bf16_mma<<<fgrid, 256, GSMEM>>>(Ao, Bo, out, MROWS, D_, KX);
}